// round 13
// baseline (speedup 1.0000x reference)
#include <cuda_runtime.h>
#include <cuda_bf16.h>
#include <cstdint>

#define NN   116
#define FIN  116
#define HIDD 256
#define RB   256                        // tile row bytes (128 bf16)
#define TILEB (128 * RB)                // 32768
#define NTHR 512

// swizzle for 256B-pitch tiles: spreads row%8 across banks, keeps 16B units
#define SWZ(o) ((uint32_t)(o) ^ (((uint32_t)(o) >> 4) & 0x70u))

// ---- SMEM byte offsets (per CTA total 82944 -> 2 CTAs/SM) ----
#define OFF_T1    0                        // x tile -> sx tile (tail scratch later)
#define OFF_T2    TILEB                    // sup tile
#define OFF_W2    (2 * TILEB)              // 256*4 f32 = 4096
#define OFF_B1V   (OFF_W2 + 4096)          // 256 f32
#define OFF_Z     (OFF_B1V + 1024)         // 128*4 f32 = 2048
#define OFF_ZP    (OFF_Z + 2048)           // 4*128*4 f32 = 8192
#define SMEM_BYTES (OFF_ZP + 8192)         // 82944

// tail scratch overlaid in T1 (sx dead after GEMM_B)
#define OFF_FLAT  OFF_T1                   // 512 f32 (464 + zero pad)
#define OFF_R     (OFF_FLAT + 2048)        // 64 f32
#define OFF_RED   (OFF_R + 256)            // 16 f32

// W1 fragment image: uint32 regs, index = ((((half*4+wc)*8+ks)*2+grp)*32+lane)*4+u
__device__ uint32_t g_w1frag[16384];       // 64KB
// pre-transposed Wr1^T: [64 rows j][512 cols i] f32 (i >= 464 zero)
__device__ float g_wr1t[64 * 512];

__device__ __forceinline__ uint32_t smem_u32(const void* p) {
    uint32_t a;
    asm("{ .reg .u64 t; cvta.to.shared.u64 t, %1; cvt.u32.u64 %0, t; }" : "=r"(a) : "l"(p));
    return a;
}
__device__ __forceinline__ uint32_t pack_bf16(float a, float b) {
    __nv_bfloat162 v = __float22bfloat162_rn(make_float2(a, b));
    return *(uint32_t*)&v;
}
__device__ __forceinline__ float bf_lo(uint32_t w) {
    return __bfloat162float(__ushort_as_bfloat16((unsigned short)(w & 0xffff)));
}
__device__ __forceinline__ float bf_hi(uint32_t w) {
    return __bfloat162float(__ushort_as_bfloat16((unsigned short)(w >> 16)));
}

#define BAR_SYNC(id, cnt) asm volatile("bar.sync %0, %1;" :: "r"(id), "r"(cnt) : "memory")

#define LDSM_X4(r0, r1, r2, r3, addr) \
    asm volatile("ldmatrix.sync.aligned.m8n8.x4.shared.b16 {%0,%1,%2,%3}, [%4];" \
        : "=r"(r0), "=r"(r1), "=r"(r2), "=r"(r3) : "r"(addr))
#define LDSM_X4T(r0, r1, r2, r3, addr) \
    asm volatile("ldmatrix.sync.aligned.m8n8.x4.trans.shared.b16 {%0,%1,%2,%3}, [%4];" \
        : "=r"(r0), "=r"(r1), "=r"(r2), "=r"(r3) : "r"(addr))

__device__ __forceinline__ void mma16816(float* d, uint32_t a0, uint32_t a1,
                                         uint32_t a2, uint32_t a3,
                                         uint32_t b0, uint32_t b1) {
    asm volatile(
        "mma.sync.aligned.m16n8k16.row.col.f32.bf16.bf16.f32 "
        "{%0,%1,%2,%3}, {%4,%5,%6,%7}, {%8,%9}, {%0,%1,%2,%3};"
        : "+f"(d[0]), "+f"(d[1]), "+f"(d[2]), "+f"(d[3])
        : "r"(a0), "r"(a1), "r"(a2), "r"(a3), "r"(b0), "r"(b1));
}

// GEMM, warp tile 32x32, B from SMEM K-major [k][n] via trans LDSM (GEMM_A)
__device__ __forceinline__ void mma32(float acc[2][4][4],
                                      uint32_t aTile, uint32_t bTile,
                                      int r0, int c0, int lane) {
    const int row_in = (lane & 7) | (((lane >> 3) & 1) << 3);
    const int col_in = (lane >> 4) << 3;
    const uint32_t aRel0 = (uint32_t)((r0 + row_in) * RB + col_in * 2);
    const uint32_t aRel1 = aRel0 + 16 * RB;
    const uint32_t mA0 = (aRel0 >> 4) & 0x70u;
    const uint32_t mA1 = (aRel1 >> 4) & 0x70u;
    const uint32_t bRel0 = (uint32_t)(row_in * RB + (c0 + col_in) * 2);
    const uint32_t bRel1 = bRel0 + 32;
    uint32_t b0 = bTile + SWZ(bRel0);
    uint32_t b1 = bTile + SWZ(bRel1);
    #pragma unroll
    for (int k = 0; k < 8; ++k) {
        const uint32_t ca = (uint32_t)(k * 32);
        uint32_t a0, a1, a2, a3, a4, a5, a6, a7;
        LDSM_X4(a0, a1, a2, a3, aTile + ((aRel0 + ca) ^ mA0));
        LDSM_X4(a4, a5, a6, a7, aTile + ((aRel1 + ca) ^ mA1));
        uint32_t p0, p1, p2, p3, q0, q1, q2, q3;
        LDSM_X4T(p0, p1, p2, p3, b0);
        LDSM_X4T(q0, q1, q2, q3, b1);
        mma16816(acc[0][0], a0, a1, a2, a3, p0, p1);
        mma16816(acc[0][1], a0, a1, a2, a3, p2, p3);
        mma16816(acc[0][2], a0, a1, a2, a3, q0, q1);
        mma16816(acc[0][3], a0, a1, a2, a3, q2, q3);
        mma16816(acc[1][0], a4, a5, a6, a7, p0, p1);
        mma16816(acc[1][1], a4, a5, a6, a7, p2, p3);
        mma16816(acc[1][2], a4, a5, a6, a7, q0, q1);
        mma16816(acc[1][3], a4, a5, a6, a7, q2, q3);
        b0 += 16 * RB;      // +16 k-rows (mask bits invariant)
        b1 += 16 * RB;
    }
}

// GEMM, warp tile 32x32, B fragments streamed from global image via LDG.128
__device__ __forceinline__ void mma32_gB(float acc[2][4][4],
                                         uint32_t aTile, const uint4* wfrag,
                                         int r0, int lane) {
    const int row_in = (lane & 7) | (((lane >> 3) & 1) << 3);
    const int col_in = (lane >> 4) << 3;
    const uint32_t aRel0 = (uint32_t)((r0 + row_in) * RB + col_in * 2);
    const uint32_t aRel1 = aRel0 + 16 * RB;
    const uint32_t mA0 = (aRel0 >> 4) & 0x70u;
    const uint32_t mA1 = (aRel1 >> 4) & 0x70u;
    #pragma unroll
    for (int k = 0; k < 8; ++k) {
        const uint32_t ca = (uint32_t)(k * 32);
        uint32_t a0, a1, a2, a3, a4, a5, a6, a7;
        LDSM_X4(a0, a1, a2, a3, aTile + ((aRel0 + ca) ^ mA0));
        LDSM_X4(a4, a5, a6, a7, aTile + ((aRel1 + ca) ^ mA1));
        uint4 g0 = wfrag[k * 64 + lane];        // regs p0..p3 (coalesced 512B)
        uint4 g1 = wfrag[k * 64 + 32 + lane];   // regs q0..q3
        mma16816(acc[0][0], a0, a1, a2, a3, g0.x, g0.y);
        mma16816(acc[0][1], a0, a1, a2, a3, g0.z, g0.w);
        mma16816(acc[0][2], a0, a1, a2, a3, g1.x, g1.y);
        mma16816(acc[0][3], a0, a1, a2, a3, g1.z, g1.w);
        mma16816(acc[1][0], a4, a5, a6, a7, g0.x, g0.y);
        mma16816(acc[1][1], a4, a5, a6, a7, g0.z, g0.w);
        mma16816(acc[1][2], a4, a5, a6, a7, g1.x, g1.y);
        mma16816(acc[1][3], a4, a5, a6, a7, g1.z, g1.w);
    }
}

// ---- fused prep: W1 fragment image + Wr1^T (idempotent) ----
__global__ void prep_weights(const float* __restrict__ W1,
                             const float* __restrict__ Wr1) {
    int idx = blockIdx.x * blockDim.x + threadIdx.x;
    if (idx < 16384) {
        int u    = idx & 3;
        int lane = (idx >> 2) & 31;
        int grp  = (idx >> 7) & 1;
        int ks   = (idx >> 8) & 7;
        int wc   = (idx >> 11) & 3;
        int half = idx >> 13;
        int r = grp * 4 + u;
        int k = ks * 16 + (r & 1) * 8 + (lane & 3) * 2;
        int h = half * 128 + wc * 32 + (r >> 1) * 8 + (lane >> 2);
        float v0 = (k     < FIN) ? W1[(size_t)k * HIDD + h]       : 0.f;
        float v1 = (k + 1 < FIN) ? W1[(size_t)(k + 1) * HIDD + h] : 0.f;
        g_w1frag[idx] = pack_bf16(v0, v1);
    } else if (idx < 16384 + 64 * 512) {
        int q = idx - 16384;
        int j = q >> 9, i = q & 511;
        g_wr1t[q] = (i < 464) ? Wr1[(size_t)i * 64 + j] : 0.f;
    }
}

extern __shared__ char smc[];

__global__ void __launch_bounds__(NTHR, 2) gcn_mma(
    const float* __restrict__ x,   const float* __restrict__ sup,
    const float* __restrict__ W1,  const float* __restrict__ b1,
    const float* __restrict__ W2,  const float* __restrict__ b2,
    const float* __restrict__ Wr1, const float* __restrict__ br1,
    const float* __restrict__ Wr2, const float* __restrict__ br2,
    float* __restrict__ out)
{
    const int tid  = threadIdx.x;
    const int b    = blockIdx.x;
    const int lane = tid & 31;
    const int warp = tid >> 5;            // 0..15
    const int r0   = (warp >> 2) * 32;    // 4 row blocks
    const int c0   = (warp & 3) * 32;     // 4 col blocks
    const int wc   = warp & 3;

    float* s_w2   = (float*)(smc + OFF_W2);
    float* s_b1   = (float*)(smc + OFF_B1V);
    float* s_z    = (float*)(smc + OFF_Z);
    float* s_zp   = (float*)(smc + OFF_ZP);
    float* s_flat = (float*)(smc + OFF_FLAT);
    float* s_r    = (float*)(smc + OFF_R);
    float* s_red  = (float*)(smc + OFF_RED);

    const uint32_t su = smem_u32(smc);

    // zero ONLY the pad regions of x/sup tiles:
    //  (a) full rows 116..127
    const uint4 z4 = make_uint4(0, 0, 0, 0);
    for (int i = tid; i < 12 * 16 * 2; i += NTHR) {
        int t   = i / (12 * 16);
        int rem = i % (12 * 16);
        int m = 116 + (rem >> 4), u = rem & 15;
        *(uint4*)(smc + (t ? OFF_T2 : OFF_T1) + (uint32_t)(m * RB + u * 16)) = z4;
    }
    //  (b) cols 112..127 of rows 0..115 (2 swizzled 16B units; converter
    //      overwrites bytes 224..231 after the barrier)
    for (int i = tid; i < 116 * 2 * 2; i += NTHR) {
        int t   = i & 1;
        int rem = i >> 1;
        int m = rem >> 1, u = rem & 1;
        uint32_t off = SWZ((uint32_t)(m * RB + 224 + u * 16));
        *(uint4*)(smc + (t ? OFF_T2 : OFF_T1) + off) = z4;
    }
    for (int i = tid; i < HIDD * 4; i += NTHR) s_w2[i] = W2[i];
    for (int i = tid; i < HIDD; i += NTHR)     s_b1[i] = b1[i];
    __syncthreads();

    // load + convert x[b], sup[b] -> bf16 swizzled tiles [m][k]
    // q grid: m = q>>5, c-chunk = q&31 (guard <29); no integer divides.
    const float* xb = x   + (size_t)b * NN * FIN;
    const float* sb = sup + (size_t)b * NN * NN;
    for (int q = tid; q < NN * 32; q += NTHR) {
        int cu = q & 31;
        if (cu < 29) {
            int m = q >> 5, c4 = cu * 4;
            uint32_t off = SWZ((uint32_t)(m * RB + c4 * 2));
            float4 vx = *(const float4*)(xb + m * FIN + c4);
            uint2 w;
            w.x = pack_bf16(vx.x, vx.y);
            w.y = pack_bf16(vx.z, vx.w);
            *(uint2*)(smc + OFF_T1 + off) = w;
            float4 vs = *(const float4*)(sb + m * NN + c4);
            w.x = pack_bf16(vs.x, vs.y);
            w.y = pack_bf16(vs.z, vs.w);
            *(uint2*)(smc + OFF_T2 + off) = w;
        }
    }
    __syncthreads();

    // ---- GEMM_A: sx = sup @ x  (A = T2, B = T1 K-major, trans LDSM) ----
    {
        float acc[2][4][4];
        #pragma unroll
        for (int i = 0; i < 2; i++)
            #pragma unroll
            for (int j = 0; j < 4; j++)
                #pragma unroll
                for (int d = 0; d < 4; d++) acc[i][j][d] = 0.f;

        mma32(acc, su + OFF_T2, su + OFF_T1, r0, c0, lane);

        // x col-block c0 is read & rewritten ONLY by the 4 warps sharing wc:
        // named barrier among them instead of a full CTA sync.
        BAR_SYNC(wc + 1, 128);

        // store sx as bf16 into T1 ([n][f] layout = A of GEMM_B)
        int grow = lane >> 2, gcol = (lane & 3) * 2;
        #pragma unroll
        for (int i = 0; i < 2; i++) {
            #pragma unroll
            for (int j = 0; j < 4; j++) {
                int rr = r0 + i * 16 + grow;
                int cc = c0 + j * 8 + gcol;
                *(uint32_t*)(smc + OFF_T1 + SWZ((uint32_t)(rr * RB + cc * 2))) =
                    pack_bf16(acc[i][j][0], acc[i][j][1]);
                *(uint32_t*)(smc + OFF_T1 + SWZ((uint32_t)((rr + 8) * RB + cc * 2))) =
                    pack_bf16(acc[i][j][2], acc[i][j][3]);
            }
        }
    }
    __syncthreads();   // all sx visible to all warps

    // ---- GEMM_B both halves, no syncs: h1 = sx @ W1 (B frags from global) ----
    float zacc[4][4];
    #pragma unroll
    for (int s = 0; s < 4; s++)
        #pragma unroll
        for (int o = 0; o < 4; o++) zacc[s][o] = 0.f;

    #pragma unroll
    for (int half = 0; half < 2; ++half) {
        float acc[2][4][4];
        #pragma unroll
        for (int i = 0; i < 2; i++)
            #pragma unroll
            for (int j = 0; j < 4; j++)
                #pragma unroll
                for (int d = 0; d < 4; d++) acc[i][j][d] = 0.f;

        const uint4* wfrag = (const uint4*)g_w1frag + (size_t)(half * 4 + wc) * 512;
        mma32_gB(acc, su + OFF_T1, wfrag, r0, lane);

        // epilogue: relu(h1 + b1) contracted with W2 -> zacc (regs, both halves)
        int gcol = (lane & 3) * 2;
        #pragma unroll
        for (int i = 0; i < 2; i++) {
            #pragma unroll
            for (int j = 0; j < 4; j++) {
                int h = half * 128 + c0 + j * 8 + gcol;
                float b1a = s_b1[h], b1b = s_b1[h + 1];
                float4 wa = *(const float4*)&s_w2[h * 4];
                float4 wb = *(const float4*)&s_w2[(h + 1) * 4];
                float v0 = fmaxf(acc[i][j][0] + b1a, 0.f);
                float v1 = fmaxf(acc[i][j][1] + b1b, 0.f);
                float v2 = fmaxf(acc[i][j][2] + b1a, 0.f);
                float v3 = fmaxf(acc[i][j][3] + b1b, 0.f);
                zacc[i*2+0][0] += v0 * wa.x + v1 * wb.x;
                zacc[i*2+0][1] += v0 * wa.y + v1 * wb.y;
                zacc[i*2+0][2] += v0 * wa.z + v1 * wb.z;
                zacc[i*2+0][3] += v0 * wa.w + v1 * wb.w;
                zacc[i*2+1][0] += v2 * wa.x + v3 * wb.x;
                zacc[i*2+1][1] += v2 * wa.y + v3 * wb.y;
                zacc[i*2+1][2] += v2 * wa.z + v3 * wb.z;
                zacc[i*2+1][3] += v2 * wa.w + v3 * wb.w;
            }
        }
    }

    // reduce zacc over the 4 lanes sharing the same rows; single zp write
    #pragma unroll
    for (int s = 0; s < 4; s++) {
        #pragma unroll
        for (int o = 0; o < 4; o++) {
            float v = zacc[s][o];
            v += __shfl_xor_sync(0xffffffffu, v, 1);
            v += __shfl_xor_sync(0xffffffffu, v, 2);
            zacc[s][o] = v;
        }
    }
    if ((lane & 3) == 0) {
        #pragma unroll
        for (int s = 0; s < 4; s++) {
            int rr = r0 + (s >> 1) * 16 + (lane >> 2) + (s & 1) * 8;
            #pragma unroll
            for (int o = 0; o < 4; o++)
                s_zp[(wc * 128 + rr) * 4 + o] = zacc[s][o];
        }
    }
    __syncthreads();   // GEMMs done; T1 becomes tail scratch

    // z[n][o] = sum over the 4 column-group partials
    {
        int n = tid >> 2, o = tid & 3;   // exactly 512 items
        s_z[n * 4 + o] = s_zp[(0 * 128 + n) * 4 + o] + s_zp[(1 * 128 + n) * 4 + o]
                       + s_zp[(2 * 128 + n) * 4 + o] + s_zp[(3 * 128 + n) * 4 + o];
    }
    __syncthreads();

    // h2 = relu(sup @ z + b2) -> flat[464], pad to 512 with zeros
    if (tid < NN * 4) {
        int n = tid >> 2, o = tid & 3;
        float acc2 = 0.f;
        #pragma unroll
        for (int u = 0; u < 16; u++) {
            uint4 uw = *(const uint4*)(smc + OFF_T2 + SWZ((uint32_t)(n * RB + u * 16)));
            uint32_t wv[4] = {uw.x, uw.y, uw.z, uw.w};
            #pragma unroll
            for (int p = 0; p < 4; p++) {
                int m0 = u * 8 + p * 2;
                acc2 += bf_lo(wv[p]) * s_z[m0 * 4 + o] + bf_hi(wv[p]) * s_z[(m0 + 1) * 4 + o];
            }
        }
        s_flat[tid] = fmaxf(acc2 + b2[o], 0.f);
    } else {
        s_flat[tid] = 0.f;
    }
    __syncthreads();

    // r = relu(flat @ Wr1 + br1): warp w handles j = w*4..w*4+3; 32 lanes read
    // one 2KB row of Wr1^T coalesced (float4) and shfl-reduce.
    {
        const float4* fl4 = (const float4*)s_flat;   // 128 float4
        #pragma unroll
        for (int jj = 0; jj < 4; ++jj) {
            int j = warp * 4 + jj;
            const float4* wrow = (const float4*)(g_wr1t + (size_t)j * 512);
            float a = 0.f;
            #pragma unroll
            for (int u = 0; u < 4; ++u) {
                float4 w4 = wrow[lane + u * 32];
                float4 f4 = fl4[lane + u * 32];
                a += w4.x * f4.x + w4.y * f4.y + w4.z * f4.z + w4.w * f4.w;
            }
            a += __shfl_xor_sync(0xffffffffu, a, 16);
            a += __shfl_xor_sync(0xffffffffu, a, 8);
            a += __shfl_xor_sync(0xffffffffu, a, 4);
            a += __shfl_xor_sync(0xffffffffu, a, 2);
            a += __shfl_xor_sync(0xffffffffu, a, 1);
            if (lane == 0) s_r[j] = fmaxf(a + br1[j], 0.f);
        }
    }
    __syncthreads();

    // logits = r @ Wr2 + br2 ; log_softmax (2 classes)
    if (tid < 64) {
        float rv = s_r[tid];
        float p0 = rv * Wr2[tid * 2 + 0];
        float p1 = rv * Wr2[tid * 2 + 1];
        #pragma unroll
        for (int m = 16; m >= 1; m >>= 1) {
            p0 += __shfl_xor_sync(0xffffffffu, p0, m);
            p1 += __shfl_xor_sync(0xffffffffu, p1, m);
        }
        if ((tid & 31) == 0) {
            s_red[(tid >> 5) * 2 + 0] = p0;
            s_red[(tid >> 5) * 2 + 1] = p1;
        }
    }
    __syncthreads();
    if (tid == 0) {
        float l0 = s_red[0] + s_red[2] + br2[0];
        float l1 = s_red[1] + s_red[3] + br2[1];
        float mx = fmaxf(l0, l1);
        float lse = mx + logf(expf(l0 - mx) + expf(l1 - mx));
        out[(size_t)b * 2 + 0] = l0 - lse;
        out[(size_t)b * 2 + 1] = l1 - lse;
    }
}

extern "C" void kernel_launch(void* const* d_in, const int* in_sizes, int n_in,
                              void* d_out, int out_size) {
    const float* x   = (const float*)d_in[0];
    const float* sup = (const float*)d_in[1];
    const float* W1  = (const float*)d_in[2];
    const float* b1  = (const float*)d_in[3];
    const float* W2  = (const float*)d_in[4];
    const float* b2  = (const float*)d_in[5];
    const float* Wr1 = (const float*)d_in[6];
    const float* br1 = (const float*)d_in[7];
    const float* Wr2 = (const float*)d_in[8];
    const float* br2 = (const float*)d_in[9];
    float* out = (float*)d_out;

    int B = in_sizes[0] / (NN * FIN);

    prep_weights<<<(16384 + 64 * 512 + 255) / 256, 256>>>(W1, Wr1);

    cudaFuncSetAttribute(gcn_mma, cudaFuncAttributeMaxDynamicSharedMemorySize, SMEM_BYTES);
    gcn_mma<<<B, NTHR, SMEM_BYTES>>>(x, sup, W1, b1, W2, b2, Wr1, br1, Wr2, br2, out);
}

// round 14
// speedup vs baseline: 2.2700x; 2.2700x over previous
#include <cuda_runtime.h>
#include <cuda_bf16.h>
#include <cstdint>

#define NN   116
#define FIN  116
#define HIDD 256
#define RB   256                        // tile row bytes (128 bf16)
#define TILEB (128 * RB)                // 32768
#define NTHR 512

// swizzle for 256B-pitch tiles: spreads row%8 across banks, keeps 16B units
#define SWZ(o) ((uint32_t)(o) ^ (((uint32_t)(o) >> 4) & 0x70u))

// ---- SMEM byte offsets (per CTA total 82944 -> 2 CTAs/SM) ----
#define OFF_T1    0                        // x tile -> sx tile (tail scratch later)
#define OFF_T2    TILEB                    // sup tile
#define OFF_W2    (2 * TILEB)              // 256*4 f32 = 4096
#define OFF_B1V   (OFF_W2 + 4096)          // 256 f32
#define OFF_Z     (OFF_B1V + 1024)         // 128*4 f32 = 2048
#define OFF_ZP    (OFF_Z + 2048)           // 4*128*4 f32 = 8192
#define SMEM_BYTES (OFF_ZP + 8192)         // 82944

// tail scratch overlaid in T1 (sx dead after GEMM_B)
#define OFF_FLAT  OFF_T1                   // 512 f32 (464 + zero pad)
#define OFF_R     (OFF_FLAT + 2048)        // 64 f32
#define OFF_RED   (OFF_R + 256)            // 16 f32

// W1 fragment image: uint32 regs, index = ((((half*4+wc)*8+ks)*2+grp)*32+lane)*4+u
__device__ uint32_t g_w1frag[16384];       // 64KB
// pre-transposed Wr1^T: [64 rows j][512 cols i] f32 (i >= 464 zero)
__device__ float g_wr1t[64 * 512];

__device__ __forceinline__ uint32_t smem_u32(const void* p) {
    uint32_t a;
    asm("{ .reg .u64 t; cvta.to.shared.u64 t, %1; cvt.u32.u64 %0, t; }" : "=r"(a) : "l"(p));
    return a;
}
__device__ __forceinline__ uint32_t pack_bf16(float a, float b) {
    __nv_bfloat162 v = __float22bfloat162_rn(make_float2(a, b));
    return *(uint32_t*)&v;
}
__device__ __forceinline__ float bf_lo(uint32_t w) {
    return __bfloat162float(__ushort_as_bfloat16((unsigned short)(w & 0xffff)));
}
__device__ __forceinline__ float bf_hi(uint32_t w) {
    return __bfloat162float(__ushort_as_bfloat16((unsigned short)(w >> 16)));
}

#define BAR_SYNC(id, cnt) asm volatile("bar.sync %0, %1;" :: "r"(id), "r"(cnt) : "memory")

#define LDSM_X4(r0, r1, r2, r3, addr) \
    asm volatile("ldmatrix.sync.aligned.m8n8.x4.shared.b16 {%0,%1,%2,%3}, [%4];" \
        : "=r"(r0), "=r"(r1), "=r"(r2), "=r"(r3) : "r"(addr))
#define LDSM_X4T(r0, r1, r2, r3, addr) \
    asm volatile("ldmatrix.sync.aligned.m8n8.x4.trans.shared.b16 {%0,%1,%2,%3}, [%4];" \
        : "=r"(r0), "=r"(r1), "=r"(r2), "=r"(r3) : "r"(addr))

__device__ __forceinline__ void mma16816(float* d, uint32_t a0, uint32_t a1,
                                         uint32_t a2, uint32_t a3,
                                         uint32_t b0, uint32_t b1) {
    asm volatile(
        "mma.sync.aligned.m16n8k16.row.col.f32.bf16.bf16.f32 "
        "{%0,%1,%2,%3}, {%4,%5,%6,%7}, {%8,%9}, {%0,%1,%2,%3};"
        : "+f"(d[0]), "+f"(d[1]), "+f"(d[2]), "+f"(d[3])
        : "r"(a0), "r"(a1), "r"(a2), "r"(a3), "r"(b0), "r"(b1));
}

// GEMM, warp tile 32x32, B from SMEM K-major [k][n] via trans LDSM (GEMM_A)
__device__ __forceinline__ void mma32(float acc[2][4][4],
                                      uint32_t aTile, uint32_t bTile,
                                      int r0, int c0, int lane) {
    const int row_in = (lane & 7) | (((lane >> 3) & 1) << 3);
    const int col_in = (lane >> 4) << 3;
    const uint32_t aRel0 = (uint32_t)((r0 + row_in) * RB + col_in * 2);
    const uint32_t aRel1 = aRel0 + 16 * RB;
    const uint32_t mA0 = (aRel0 >> 4) & 0x70u;
    const uint32_t mA1 = (aRel1 >> 4) & 0x70u;
    const uint32_t bRel0 = (uint32_t)(row_in * RB + (c0 + col_in) * 2);
    const uint32_t bRel1 = bRel0 + 32;
    uint32_t b0 = bTile + SWZ(bRel0);
    uint32_t b1 = bTile + SWZ(bRel1);
    #pragma unroll
    for (int k = 0; k < 8; ++k) {
        const uint32_t ca = (uint32_t)(k * 32);
        uint32_t a0, a1, a2, a3, a4, a5, a6, a7;
        LDSM_X4(a0, a1, a2, a3, aTile + ((aRel0 + ca) ^ mA0));
        LDSM_X4(a4, a5, a6, a7, aTile + ((aRel1 + ca) ^ mA1));
        uint32_t p0, p1, p2, p3, q0, q1, q2, q3;
        LDSM_X4T(p0, p1, p2, p3, b0);
        LDSM_X4T(q0, q1, q2, q3, b1);
        mma16816(acc[0][0], a0, a1, a2, a3, p0, p1);
        mma16816(acc[0][1], a0, a1, a2, a3, p2, p3);
        mma16816(acc[0][2], a0, a1, a2, a3, q0, q1);
        mma16816(acc[0][3], a0, a1, a2, a3, q2, q3);
        mma16816(acc[1][0], a4, a5, a6, a7, p0, p1);
        mma16816(acc[1][1], a4, a5, a6, a7, p2, p3);
        mma16816(acc[1][2], a4, a5, a6, a7, q0, q1);
        mma16816(acc[1][3], a4, a5, a6, a7, q2, q3);
        b0 += 16 * RB;      // +16 k-rows (mask bits invariant)
        b1 += 16 * RB;
    }
}

// GEMM, warp tile 32x32, B fragments streamed from global image via LDG.128
__device__ __forceinline__ void mma32_gB(float acc[2][4][4],
                                         uint32_t aTile, const uint4* wfrag,
                                         int r0, int lane) {
    const int row_in = (lane & 7) | (((lane >> 3) & 1) << 3);
    const int col_in = (lane >> 4) << 3;
    const uint32_t aRel0 = (uint32_t)((r0 + row_in) * RB + col_in * 2);
    const uint32_t aRel1 = aRel0 + 16 * RB;
    const uint32_t mA0 = (aRel0 >> 4) & 0x70u;
    const uint32_t mA1 = (aRel1 >> 4) & 0x70u;
    #pragma unroll
    for (int k = 0; k < 8; ++k) {
        const uint32_t ca = (uint32_t)(k * 32);
        uint32_t a0, a1, a2, a3, a4, a5, a6, a7;
        LDSM_X4(a0, a1, a2, a3, aTile + ((aRel0 + ca) ^ mA0));
        LDSM_X4(a4, a5, a6, a7, aTile + ((aRel1 + ca) ^ mA1));
        uint4 g0 = wfrag[k * 64 + lane];        // regs p0..p3 (coalesced 512B)
        uint4 g1 = wfrag[k * 64 + 32 + lane];   // regs q0..q3
        mma16816(acc[0][0], a0, a1, a2, a3, g0.x, g0.y);
        mma16816(acc[0][1], a0, a1, a2, a3, g0.z, g0.w);
        mma16816(acc[0][2], a0, a1, a2, a3, g1.x, g1.y);
        mma16816(acc[0][3], a0, a1, a2, a3, g1.z, g1.w);
        mma16816(acc[1][0], a4, a5, a6, a7, g0.x, g0.y);
        mma16816(acc[1][1], a4, a5, a6, a7, g0.z, g0.w);
        mma16816(acc[1][2], a4, a5, a6, a7, g1.x, g1.y);
        mma16816(acc[1][3], a4, a5, a6, a7, g1.z, g1.w);
    }
}

// ---- fused prep: W1 fragment image + Wr1^T (idempotent) ----
__global__ void prep_weights(const float* __restrict__ W1,
                             const float* __restrict__ Wr1) {
    int idx = blockIdx.x * blockDim.x + threadIdx.x;
    if (idx < 16384) {
        int u    = idx & 3;
        int lane = (idx >> 2) & 31;
        int grp  = (idx >> 7) & 1;
        int ks   = (idx >> 8) & 7;
        int wc   = (idx >> 11) & 3;
        int half = idx >> 13;
        int r = grp * 4 + u;
        int k = ks * 16 + (r & 1) * 8 + (lane & 3) * 2;
        int h = half * 128 + wc * 32 + (r >> 1) * 8 + (lane >> 2);
        float v0 = (k     < FIN) ? W1[(size_t)k * HIDD + h]       : 0.f;
        float v1 = (k + 1 < FIN) ? W1[(size_t)(k + 1) * HIDD + h] : 0.f;
        g_w1frag[idx] = pack_bf16(v0, v1);
    } else if (idx < 16384 + 64 * 512) {
        int q = idx - 16384;
        int j = q >> 9, i = q & 511;
        g_wr1t[q] = (i < 464) ? Wr1[(size_t)i * 64 + j] : 0.f;
    }
}

extern __shared__ char smc[];

__global__ void __launch_bounds__(NTHR, 2) gcn_mma(
    const float* __restrict__ x,   const float* __restrict__ sup,
    const float* __restrict__ W1,  const float* __restrict__ b1,
    const float* __restrict__ W2,  const float* __restrict__ b2,
    const float* __restrict__ Wr1, const float* __restrict__ br1,
    const float* __restrict__ Wr2, const float* __restrict__ br2,
    float* __restrict__ out)
{
    const int tid  = threadIdx.x;
    const int b    = blockIdx.x;
    const int lane = tid & 31;
    const int warp = tid >> 5;            // 0..15
    const int r0   = (warp >> 2) * 32;    // 4 row blocks
    const int c0   = (warp & 3) * 32;     // 4 col blocks
    const int wc   = warp & 3;

    float* s_w2   = (float*)(smc + OFF_W2);
    float* s_b1   = (float*)(smc + OFF_B1V);
    float* s_z    = (float*)(smc + OFF_Z);
    float* s_zp   = (float*)(smc + OFF_ZP);
    float* s_flat = (float*)(smc + OFF_FLAT);
    float* s_r    = (float*)(smc + OFF_R);
    float* s_red  = (float*)(smc + OFF_RED);

    const uint32_t su = smem_u32(smc);

    // zero ONLY the pad regions of x/sup tiles:
    //  (a) full rows 116..127
    const uint4 z4 = make_uint4(0, 0, 0, 0);
    for (int i = tid; i < 12 * 16 * 2; i += NTHR) {
        int t   = i / (12 * 16);
        int rem = i % (12 * 16);
        int m = 116 + (rem >> 4), u = rem & 15;
        *(uint4*)(smc + (t ? OFF_T2 : OFF_T1) + (uint32_t)(m * RB + u * 16)) = z4;
    }
    //  (b) cols 112..127 of rows 0..115 (2 swizzled 16B units; converter
    //      overwrites bytes 224..231 after the barrier)
    for (int i = tid; i < 116 * 2 * 2; i += NTHR) {
        int t   = i & 1;
        int rem = i >> 1;
        int m = rem >> 1, u = rem & 1;
        uint32_t off = SWZ((uint32_t)(m * RB + 224 + u * 16));
        *(uint4*)(smc + (t ? OFF_T2 : OFF_T1) + off) = z4;
    }
    for (int i = tid; i < HIDD * 4; i += NTHR) s_w2[i] = W2[i];
    for (int i = tid; i < HIDD; i += NTHR)     s_b1[i] = b1[i];
    __syncthreads();

    // load + convert x[b], sup[b] -> bf16 swizzled tiles [m][k]
    // q grid: m = q>>5, c-chunk = q&31 (guard <29); no integer divides.
    const float* xb = x   + (size_t)b * NN * FIN;
    const float* sb = sup + (size_t)b * NN * NN;
    for (int q = tid; q < NN * 32; q += NTHR) {
        int cu = q & 31;
        if (cu < 29) {
            int m = q >> 5, c4 = cu * 4;
            uint32_t off = SWZ((uint32_t)(m * RB + c4 * 2));
            float4 vx = *(const float4*)(xb + m * FIN + c4);
            uint2 w;
            w.x = pack_bf16(vx.x, vx.y);
            w.y = pack_bf16(vx.z, vx.w);
            *(uint2*)(smc + OFF_T1 + off) = w;
            float4 vs = *(const float4*)(sb + m * NN + c4);
            w.x = pack_bf16(vs.x, vs.y);
            w.y = pack_bf16(vs.z, vs.w);
            *(uint2*)(smc + OFF_T2 + off) = w;
        }
    }
    __syncthreads();

    // ---- GEMM_A: sx = sup @ x  (A = T2, B = T1 K-major, trans LDSM) ----
    {
        float acc[2][4][4];
        #pragma unroll
        for (int i = 0; i < 2; i++)
            #pragma unroll
            for (int j = 0; j < 4; j++)
                #pragma unroll
                for (int d = 0; d < 4; d++) acc[i][j][d] = 0.f;

        mma32(acc, su + OFF_T2, su + OFF_T1, r0, c0, lane);

        // x col-block c0 is read & rewritten ONLY by the 4 warps sharing wc:
        // named barrier among them instead of a full CTA sync.
        BAR_SYNC(wc + 1, 128);

        // store sx as bf16 into T1 ([n][f] layout = A of GEMM_B)
        int grow = lane >> 2, gcol = (lane & 3) * 2;
        #pragma unroll
        for (int i = 0; i < 2; i++) {
            #pragma unroll
            for (int j = 0; j < 4; j++) {
                int rr = r0 + i * 16 + grow;
                int cc = c0 + j * 8 + gcol;
                *(uint32_t*)(smc + OFF_T1 + SWZ((uint32_t)(rr * RB + cc * 2))) =
                    pack_bf16(acc[i][j][0], acc[i][j][1]);
                *(uint32_t*)(smc + OFF_T1 + SWZ((uint32_t)((rr + 8) * RB + cc * 2))) =
                    pack_bf16(acc[i][j][2], acc[i][j][3]);
            }
        }
    }
    __syncthreads();   // all sx visible to all warps

    // ---- GEMM_B both halves, no internal syncs (B frags from global) ----
    #pragma unroll
    for (int half = 0; half < 2; ++half) {
        float acc[2][4][4];
        #pragma unroll
        for (int i = 0; i < 2; i++)
            #pragma unroll
            for (int j = 0; j < 4; j++)
                #pragma unroll
                for (int d = 0; d < 4; d++) acc[i][j][d] = 0.f;

        const uint4* wfrag = (const uint4*)g_w1frag + (size_t)(half * 4 + wc) * 512;
        mma32_gB(acc, su + OFF_T1, wfrag, r0, lane);

        // epilogue: relu(h1 + b1) contracted with W2 -> zacc -> s_zp
        // (zacc lives ONLY inside this half: keeps regs at 64, no spills)
        float zacc[4][4];
        #pragma unroll
        for (int s = 0; s < 4; s++)
            #pragma unroll
            for (int o = 0; o < 4; o++) zacc[s][o] = 0.f;
        {
            int gcol = (lane & 3) * 2;
            #pragma unroll
            for (int i = 0; i < 2; i++) {
                #pragma unroll
                for (int j = 0; j < 4; j++) {
                    int h = half * 128 + c0 + j * 8 + gcol;
                    float b1a = s_b1[h], b1b = s_b1[h + 1];
                    float4 wa = *(const float4*)&s_w2[h * 4];
                    float4 wb = *(const float4*)&s_w2[(h + 1) * 4];
                    float v0 = fmaxf(acc[i][j][0] + b1a, 0.f);
                    float v1 = fmaxf(acc[i][j][1] + b1b, 0.f);
                    float v2 = fmaxf(acc[i][j][2] + b1a, 0.f);
                    float v3 = fmaxf(acc[i][j][3] + b1b, 0.f);
                    zacc[i*2+0][0] += v0 * wa.x + v1 * wb.x;
                    zacc[i*2+0][1] += v0 * wa.y + v1 * wb.y;
                    zacc[i*2+0][2] += v0 * wa.z + v1 * wb.z;
                    zacc[i*2+0][3] += v0 * wa.w + v1 * wb.w;
                    zacc[i*2+1][0] += v2 * wa.x + v3 * wb.x;
                    zacc[i*2+1][1] += v2 * wa.y + v3 * wb.y;
                    zacc[i*2+1][2] += v2 * wa.z + v3 * wb.z;
                    zacc[i*2+1][3] += v2 * wa.w + v3 * wb.w;
                }
            }
        }
        // reduce over the 4 lanes sharing the same rows; half0 assigns, half1 adds
        #pragma unroll
        for (int s = 0; s < 4; s++) {
            #pragma unroll
            for (int o = 0; o < 4; o++) {
                float v = zacc[s][o];
                v += __shfl_xor_sync(0xffffffffu, v, 1);
                v += __shfl_xor_sync(0xffffffffu, v, 2);
                zacc[s][o] = v;
            }
        }
        if ((lane & 3) == 0) {
            #pragma unroll
            for (int s = 0; s < 4; s++) {
                int rr = r0 + (s >> 1) * 16 + (lane >> 2) + (s & 1) * 8;
                #pragma unroll
                for (int o = 0; o < 4; o++) {
                    float* dst = &s_zp[(wc * 128 + rr) * 4 + o];
                    if (half == 0) *dst = zacc[s][o];
                    else           *dst += zacc[s][o];
                }
            }
        }
    }
    __syncthreads();   // GEMMs done; T1 becomes tail scratch

    // z[n][o] = sum over the 4 column-group partials
    {
        int n = tid >> 2, o = tid & 3;   // exactly 512 items
        s_z[n * 4 + o] = s_zp[(0 * 128 + n) * 4 + o] + s_zp[(1 * 128 + n) * 4 + o]
                       + s_zp[(2 * 128 + n) * 4 + o] + s_zp[(3 * 128 + n) * 4 + o];
    }
    __syncthreads();

    // h2 = relu(sup @ z + b2) -> flat[464], pad to 512 with zeros
    if (tid < NN * 4) {
        int n = tid >> 2, o = tid & 3;
        float acc2 = 0.f;
        #pragma unroll
        for (int u = 0; u < 16; u++) {
            uint4 uw = *(const uint4*)(smc + OFF_T2 + SWZ((uint32_t)(n * RB + u * 16)));
            uint32_t wv[4] = {uw.x, uw.y, uw.z, uw.w};
            #pragma unroll
            for (int p = 0; p < 4; p++) {
                int m0 = u * 8 + p * 2;
                acc2 += bf_lo(wv[p]) * s_z[m0 * 4 + o] + bf_hi(wv[p]) * s_z[(m0 + 1) * 4 + o];
            }
        }
        s_flat[tid] = fmaxf(acc2 + b2[o], 0.f);
    } else {
        s_flat[tid] = 0.f;
    }
    __syncthreads();

    // r = relu(flat @ Wr1 + br1): warp w handles j = w*4..w*4+3; 32 lanes read
    // one 2KB row of Wr1^T coalesced (float4) and shfl-reduce.
    {
        const float4* fl4 = (const float4*)s_flat;   // 128 float4
        #pragma unroll
        for (int jj = 0; jj < 4; ++jj) {
            int j = warp * 4 + jj;
            const float4* wrow = (const float4*)(g_wr1t + (size_t)j * 512);
            float a = 0.f;
            #pragma unroll
            for (int u = 0; u < 4; ++u) {
                float4 w4 = wrow[lane + u * 32];
                float4 f4 = fl4[lane + u * 32];
                a += w4.x * f4.x + w4.y * f4.y + w4.z * f4.z + w4.w * f4.w;
            }
            a += __shfl_xor_sync(0xffffffffu, a, 16);
            a += __shfl_xor_sync(0xffffffffu, a, 8);
            a += __shfl_xor_sync(0xffffffffu, a, 4);
            a += __shfl_xor_sync(0xffffffffu, a, 2);
            a += __shfl_xor_sync(0xffffffffu, a, 1);
            if (lane == 0) s_r[j] = fmaxf(a + br1[j], 0.f);
        }
    }
    __syncthreads();

    // logits = r @ Wr2 + br2 ; log_softmax (2 classes)
    if (tid < 64) {
        float rv = s_r[tid];
        float p0 = rv * Wr2[tid * 2 + 0];
        float p1 = rv * Wr2[tid * 2 + 1];
        #pragma unroll
        for (int m = 16; m >= 1; m >>= 1) {
            p0 += __shfl_xor_sync(0xffffffffu, p0, m);
            p1 += __shfl_xor_sync(0xffffffffu, p1, m);
        }
        if ((tid & 31) == 0) {
            s_red[(tid >> 5) * 2 + 0] = p0;
            s_red[(tid >> 5) * 2 + 1] = p1;
        }
    }
    __syncthreads();
    if (tid == 0) {
        float l0 = s_red[0] + s_red[2] + br2[0];
        float l1 = s_red[1] + s_red[3] + br2[1];
        float mx = fmaxf(l0, l1);
        float lse = mx + logf(expf(l0 - mx) + expf(l1 - mx));
        out[(size_t)b * 2 + 0] = l0 - lse;
        out[(size_t)b * 2 + 1] = l1 - lse;
    }
}

extern "C" void kernel_launch(void* const* d_in, const int* in_sizes, int n_in,
                              void* d_out, int out_size) {
    const float* x   = (const float*)d_in[0];
    const float* sup = (const float*)d_in[1];
    const float* W1  = (const float*)d_in[2];
    const float* b1  = (const float*)d_in[3];
    const float* W2  = (const float*)d_in[4];
    const float* b2  = (const float*)d_in[5];
    const float* Wr1 = (const float*)d_in[6];
    const float* br1 = (const float*)d_in[7];
    const float* Wr2 = (const float*)d_in[8];
    const float* br2 = (const float*)d_in[9];
    float* out = (float*)d_out;

    int B = in_sizes[0] / (NN * FIN);

    prep_weights<<<(16384 + 64 * 512 + 255) / 256, 256>>>(W1, Wr1);

    cudaFuncSetAttribute(gcn_mma, cudaFuncAttributeMaxDynamicSharedMemorySize, SMEM_BYTES);
    gcn_mma<<<B, NTHR, SMEM_BYTES>>>(x, sup, W1, b1, W2, b2, Wr1, br1, Wr2, br2, out);
}

// round 15
// speedup vs baseline: 2.3957x; 1.0554x over previous
#include <cuda_runtime.h>
#include <cuda_bf16.h>
#include <cstdint>

#define NN   116
#define FIN  116
#define HIDD 256
#define RB   256                        // tile row bytes (128 bf16)
#define TILEB (128 * RB)                // 32768
#define NTHR 512

// swizzle for 256B-pitch tiles: spreads row%8 across banks, keeps 16B units
#define SWZ(o) ((uint32_t)(o) ^ (((uint32_t)(o) >> 4) & 0x70u))

// ---- SMEM byte offsets (per CTA total 82944 -> 2 CTAs/SM) ----
#define OFF_T1    0                        // x tile -> sx tile (tail scratch later)
#define OFF_T2    TILEB                    // sup tile
#define OFF_W2    (2 * TILEB)              // 256*4 f32 = 4096
#define OFF_B1V   (OFF_W2 + 4096)          // 256 f32
#define OFF_Z     (OFF_B1V + 1024)         // 128*4 f32 = 2048
#define OFF_ZP    (OFF_Z + 2048)           // 4*128*4 f32 = 8192
#define SMEM_BYTES (OFF_ZP + 8192)         // 82944

// tail scratch overlaid in T1 (sx dead after GEMM_B)
#define OFF_FLAT  OFF_T1                   // 512 f32 (464 + zero pad)
#define OFF_R     (OFF_FLAT + 2048)        // 64 f32
#define OFF_RED   (OFF_R + 256)            // 16 f32

// W1 fragment image: uint32 regs, index = ((((half*4+wc)*8+ks)*2+grp)*32+lane)*4+u
__device__ uint32_t g_w1frag[16384];       // 64KB
// pre-transposed Wr1^T: [64 rows j][512 cols i] f32 (i >= 464 zero)
__device__ float g_wr1t[64 * 512];

__device__ __forceinline__ uint32_t smem_u32(const void* p) {
    uint32_t a;
    asm("{ .reg .u64 t; cvta.to.shared.u64 t, %1; cvt.u32.u64 %0, t; }" : "=r"(a) : "l"(p));
    return a;
}
__device__ __forceinline__ uint32_t pack_bf16(float a, float b) {
    __nv_bfloat162 v = __float22bfloat162_rn(make_float2(a, b));
    return *(uint32_t*)&v;
}
__device__ __forceinline__ float bf_lo(uint32_t w) {
    return __bfloat162float(__ushort_as_bfloat16((unsigned short)(w & 0xffff)));
}
__device__ __forceinline__ float bf_hi(uint32_t w) {
    return __bfloat162float(__ushort_as_bfloat16((unsigned short)(w >> 16)));
}

#define LDSM_X4(r0, r1, r2, r3, addr) \
    asm volatile("ldmatrix.sync.aligned.m8n8.x4.shared.b16 {%0,%1,%2,%3}, [%4];" \
        : "=r"(r0), "=r"(r1), "=r"(r2), "=r"(r3) : "r"(addr))
#define LDSM_X4T(r0, r1, r2, r3, addr) \
    asm volatile("ldmatrix.sync.aligned.m8n8.x4.trans.shared.b16 {%0,%1,%2,%3}, [%4];" \
        : "=r"(r0), "=r"(r1), "=r"(r2), "=r"(r3) : "r"(addr))

__device__ __forceinline__ void mma16816(float* d, uint32_t a0, uint32_t a1,
                                         uint32_t a2, uint32_t a3,
                                         uint32_t b0, uint32_t b1) {
    asm volatile(
        "mma.sync.aligned.m16n8k16.row.col.f32.bf16.bf16.f32 "
        "{%0,%1,%2,%3}, {%4,%5,%6,%7}, {%8,%9}, {%0,%1,%2,%3};"
        : "+f"(d[0]), "+f"(d[1]), "+f"(d[2]), "+f"(d[3])
        : "r"(a0), "r"(a1), "r"(a2), "r"(a3), "r"(b0), "r"(b1));
}

// GEMM, warp tile 32x32, B from SMEM K-major [k][n] via trans LDSM (GEMM_A)
__device__ __forceinline__ void mma32(float acc[2][4][4],
                                      uint32_t aTile, uint32_t bTile,
                                      int r0, int c0, int lane) {
    const int row_in = (lane & 7) | (((lane >> 3) & 1) << 3);
    const int col_in = (lane >> 4) << 3;
    const uint32_t aRel0 = (uint32_t)((r0 + row_in) * RB + col_in * 2);
    const uint32_t aRel1 = aRel0 + 16 * RB;
    const uint32_t mA0 = (aRel0 >> 4) & 0x70u;
    const uint32_t mA1 = (aRel1 >> 4) & 0x70u;
    const uint32_t bRel0 = (uint32_t)(row_in * RB + (c0 + col_in) * 2);
    const uint32_t bRel1 = bRel0 + 32;
    uint32_t b0 = bTile + SWZ(bRel0);
    uint32_t b1 = bTile + SWZ(bRel1);
    #pragma unroll
    for (int k = 0; k < 8; ++k) {
        const uint32_t ca = (uint32_t)(k * 32);
        uint32_t a0, a1, a2, a3, a4, a5, a6, a7;
        LDSM_X4(a0, a1, a2, a3, aTile + ((aRel0 + ca) ^ mA0));
        LDSM_X4(a4, a5, a6, a7, aTile + ((aRel1 + ca) ^ mA1));
        uint32_t p0, p1, p2, p3, q0, q1, q2, q3;
        LDSM_X4T(p0, p1, p2, p3, b0);
        LDSM_X4T(q0, q1, q2, q3, b1);
        mma16816(acc[0][0], a0, a1, a2, a3, p0, p1);
        mma16816(acc[0][1], a0, a1, a2, a3, p2, p3);
        mma16816(acc[0][2], a0, a1, a2, a3, q0, q1);
        mma16816(acc[0][3], a0, a1, a2, a3, q2, q3);
        mma16816(acc[1][0], a4, a5, a6, a7, p0, p1);
        mma16816(acc[1][1], a4, a5, a6, a7, p2, p3);
        mma16816(acc[1][2], a4, a5, a6, a7, q0, q1);
        mma16816(acc[1][3], a4, a5, a6, a7, q2, q3);
        b0 += 16 * RB;      // +16 k-rows (mask bits invariant)
        b1 += 16 * RB;
    }
}

// GEMM, warp tile 32x32, B fragments streamed from global image via LDG.128
__device__ __forceinline__ void mma32_gB(float acc[2][4][4],
                                         uint32_t aTile, const uint4* wfrag,
                                         int r0, int lane) {
    const int row_in = (lane & 7) | (((lane >> 3) & 1) << 3);
    const int col_in = (lane >> 4) << 3;
    const uint32_t aRel0 = (uint32_t)((r0 + row_in) * RB + col_in * 2);
    const uint32_t aRel1 = aRel0 + 16 * RB;
    const uint32_t mA0 = (aRel0 >> 4) & 0x70u;
    const uint32_t mA1 = (aRel1 >> 4) & 0x70u;
    #pragma unroll
    for (int k = 0; k < 8; ++k) {
        const uint32_t ca = (uint32_t)(k * 32);
        uint32_t a0, a1, a2, a3, a4, a5, a6, a7;
        LDSM_X4(a0, a1, a2, a3, aTile + ((aRel0 + ca) ^ mA0));
        LDSM_X4(a4, a5, a6, a7, aTile + ((aRel1 + ca) ^ mA1));
        uint4 g0 = wfrag[k * 64 + lane];        // regs p0..p3 (coalesced 512B)
        uint4 g1 = wfrag[k * 64 + 32 + lane];   // regs q0..q3
        mma16816(acc[0][0], a0, a1, a2, a3, g0.x, g0.y);
        mma16816(acc[0][1], a0, a1, a2, a3, g0.z, g0.w);
        mma16816(acc[0][2], a0, a1, a2, a3, g1.x, g1.y);
        mma16816(acc[0][3], a0, a1, a2, a3, g1.z, g1.w);
        mma16816(acc[1][0], a4, a5, a6, a7, g0.x, g0.y);
        mma16816(acc[1][1], a4, a5, a6, a7, g0.z, g0.w);
        mma16816(acc[1][2], a4, a5, a6, a7, g1.x, g1.y);
        mma16816(acc[1][3], a4, a5, a6, a7, g1.z, g1.w);
    }
}

// ---- fused prep: W1 fragment image + Wr1^T (idempotent) ----
__global__ void prep_weights(const float* __restrict__ W1,
                             const float* __restrict__ Wr1) {
    int idx = blockIdx.x * blockDim.x + threadIdx.x;
    if (idx < 16384) {
        int u    = idx & 3;
        int lane = (idx >> 2) & 31;
        int grp  = (idx >> 7) & 1;
        int ks   = (idx >> 8) & 7;
        int wc   = (idx >> 11) & 3;
        int half = idx >> 13;
        int r = grp * 4 + u;
        int k = ks * 16 + (r & 1) * 8 + (lane & 3) * 2;
        int h = half * 128 + wc * 32 + (r >> 1) * 8 + (lane >> 2);
        float v0 = (k     < FIN) ? W1[(size_t)k * HIDD + h]       : 0.f;
        float v1 = (k + 1 < FIN) ? W1[(size_t)(k + 1) * HIDD + h] : 0.f;
        g_w1frag[idx] = pack_bf16(v0, v1);
    } else if (idx < 16384 + 64 * 512) {
        int q = idx - 16384;
        int j = q >> 9, i = q & 511;
        g_wr1t[q] = (i < 464) ? Wr1[(size_t)i * 64 + j] : 0.f;
    }
}

extern __shared__ char smc[];

__global__ void __launch_bounds__(NTHR, 2) gcn_mma(
    const float* __restrict__ x,   const float* __restrict__ sup,
    const float* __restrict__ W1,  const float* __restrict__ b1,
    const float* __restrict__ W2,  const float* __restrict__ b2,
    const float* __restrict__ Wr1, const float* __restrict__ br1,
    const float* __restrict__ Wr2, const float* __restrict__ br2,
    float* __restrict__ out)
{
    const int tid  = threadIdx.x;
    const int b    = blockIdx.x;
    const int lane = tid & 31;
    const int warp = tid >> 5;            // 0..15
    const int r0   = (warp >> 2) * 32;    // 4 row blocks
    const int c0   = (warp & 3) * 32;     // 4 col blocks
    const int wc   = warp & 3;

    float* s_w2   = (float*)(smc + OFF_W2);
    float* s_b1   = (float*)(smc + OFF_B1V);
    float* s_z    = (float*)(smc + OFF_Z);
    float* s_zp   = (float*)(smc + OFF_ZP);
    float* s_flat = (float*)(smc + OFF_FLAT);
    float* s_r    = (float*)(smc + OFF_R);
    float* s_red  = (float*)(smc + OFF_RED);

    const uint32_t su = smem_u32(smc);

    // zero ONLY the pad regions of x/sup tiles:
    //  (a) full rows 116..127
    const uint4 z4 = make_uint4(0, 0, 0, 0);
    for (int i = tid; i < 12 * 16 * 2; i += NTHR) {
        int t   = i / (12 * 16);
        int rem = i % (12 * 16);
        int m = 116 + (rem >> 4), u = rem & 15;
        *(uint4*)(smc + (t ? OFF_T2 : OFF_T1) + (uint32_t)(m * RB + u * 16)) = z4;
    }
    //  (b) cols 112..127 of rows 0..115 (2 swizzled 16B units; converter
    //      overwrites bytes 224..231 after the barrier)
    for (int i = tid; i < 116 * 2 * 2; i += NTHR) {
        int t   = i & 1;
        int rem = i >> 1;
        int m = rem >> 1, u = rem & 1;
        uint32_t off = SWZ((uint32_t)(m * RB + 224 + u * 16));
        *(uint4*)(smc + (t ? OFF_T2 : OFF_T1) + off) = z4;
    }
    for (int i = tid; i < HIDD * 4; i += NTHR) s_w2[i] = W2[i];
    for (int i = tid; i < HIDD; i += NTHR)     s_b1[i] = b1[i];
    __syncthreads();

    // load + convert x[b], sup[b] -> bf16 swizzled tiles [m][k]
    const float* xb = x   + (size_t)b * NN * FIN;
    const float* sb = sup + (size_t)b * NN * NN;
    for (int q = tid; q < NN * 29; q += NTHR) {
        int m = q / 29, c4 = (q % 29) * 4;
        uint32_t off = SWZ((uint32_t)(m * RB + c4 * 2));
        float4 vx = *(const float4*)(xb + m * FIN + c4);
        uint2 w;
        w.x = pack_bf16(vx.x, vx.y);
        w.y = pack_bf16(vx.z, vx.w);
        *(uint2*)(smc + OFF_T1 + off) = w;
        float4 vs = *(const float4*)(sb + m * NN + c4);
        w.x = pack_bf16(vs.x, vs.y);
        w.y = pack_bf16(vs.z, vs.w);
        *(uint2*)(smc + OFF_T2 + off) = w;
    }
    __syncthreads();

    // ---- GEMM_A: sx = sup @ x  (A = T2, B = T1 K-major, trans LDSM) ----
    {
        float acc[2][4][4];
        #pragma unroll
        for (int i = 0; i < 2; i++)
            #pragma unroll
            for (int j = 0; j < 4; j++)
                #pragma unroll
                for (int d = 0; d < 4; d++) acc[i][j][d] = 0.f;

        mma32(acc, su + OFF_T2, su + OFF_T1, r0, c0, lane);
        __syncthreads();   // all x reads done before overwrite

        // store sx as bf16 into T1 ([n][f] layout = A of GEMM_B)
        int grow = lane >> 2, gcol = (lane & 3) * 2;
        #pragma unroll
        for (int i = 0; i < 2; i++) {
            #pragma unroll
            for (int j = 0; j < 4; j++) {
                int rr = r0 + i * 16 + grow;
                int cc = c0 + j * 8 + gcol;
                *(uint32_t*)(smc + OFF_T1 + SWZ((uint32_t)(rr * RB + cc * 2))) =
                    pack_bf16(acc[i][j][0], acc[i][j][1]);
                *(uint32_t*)(smc + OFF_T1 + SWZ((uint32_t)((rr + 8) * RB + cc * 2))) =
                    pack_bf16(acc[i][j][2], acc[i][j][3]);
            }
        }
    }
    __syncthreads();

    // ---- GEMM_B both halves, no internal syncs (B frags from global) ----
    #pragma unroll
    for (int half = 0; half < 2; ++half) {
        float acc[2][4][4];
        #pragma unroll
        for (int i = 0; i < 2; i++)
            #pragma unroll
            for (int j = 0; j < 4; j++)
                #pragma unroll
                for (int d = 0; d < 4; d++) acc[i][j][d] = 0.f;

        const uint4* wfrag = (const uint4*)g_w1frag + (size_t)(half * 4 + wc) * 512;
        mma32_gB(acc, su + OFF_T1, wfrag, r0, lane);

        // epilogue: relu(h1 + b1) contracted with W2 -> zacc -> s_zp
        // (zacc lives ONLY inside this half: keeps regs at 64, no spills)
        float zacc[4][4];
        #pragma unroll
        for (int s = 0; s < 4; s++)
            #pragma unroll
            for (int o = 0; o < 4; o++) zacc[s][o] = 0.f;
        {
            int gcol = (lane & 3) * 2;
            #pragma unroll
            for (int i = 0; i < 2; i++) {
                #pragma unroll
                for (int j = 0; j < 4; j++) {
                    int h = half * 128 + c0 + j * 8 + gcol;
                    float b1a = s_b1[h], b1b = s_b1[h + 1];
                    float4 wa = *(const float4*)&s_w2[h * 4];
                    float4 wb = *(const float4*)&s_w2[(h + 1) * 4];
                    float v0 = fmaxf(acc[i][j][0] + b1a, 0.f);
                    float v1 = fmaxf(acc[i][j][1] + b1b, 0.f);
                    float v2 = fmaxf(acc[i][j][2] + b1a, 0.f);
                    float v3 = fmaxf(acc[i][j][3] + b1b, 0.f);
                    zacc[i*2+0][0] += v0 * wa.x + v1 * wb.x;
                    zacc[i*2+0][1] += v0 * wa.y + v1 * wb.y;
                    zacc[i*2+0][2] += v0 * wa.z + v1 * wb.z;
                    zacc[i*2+0][3] += v0 * wa.w + v1 * wb.w;
                    zacc[i*2+1][0] += v2 * wa.x + v3 * wb.x;
                    zacc[i*2+1][1] += v2 * wa.y + v3 * wb.y;
                    zacc[i*2+1][2] += v2 * wa.z + v3 * wb.z;
                    zacc[i*2+1][3] += v2 * wa.w + v3 * wb.w;
                }
            }
        }
        // reduce over the 4 lanes sharing the same rows; half0 assigns, half1 adds
        #pragma unroll
        for (int s = 0; s < 4; s++) {
            #pragma unroll
            for (int o = 0; o < 4; o++) {
                float v = zacc[s][o];
                v += __shfl_xor_sync(0xffffffffu, v, 1);
                v += __shfl_xor_sync(0xffffffffu, v, 2);
                zacc[s][o] = v;
            }
        }
        if ((lane & 3) == 0) {
            #pragma unroll
            for (int s = 0; s < 4; s++) {
                int rr = r0 + (s >> 1) * 16 + (lane >> 2) + (s & 1) * 8;
                #pragma unroll
                for (int o = 0; o < 4; o++) {
                    float* dst = &s_zp[(wc * 128 + rr) * 4 + o];
                    if (half == 0) *dst = zacc[s][o];
                    else           *dst += zacc[s][o];
                }
            }
        }
    }
    __syncthreads();   // GEMMs done; T1 becomes tail scratch

    // z[n][o] = sum over the 4 column-group partials
    {
        int n = tid >> 2, o = tid & 3;   // exactly 512 items
        s_z[n * 4 + o] = s_zp[(0 * 128 + n) * 4 + o] + s_zp[(1 * 128 + n) * 4 + o]
                       + s_zp[(2 * 128 + n) * 4 + o] + s_zp[(3 * 128 + n) * 4 + o];
    }
    __syncthreads();

    // h2 = relu(sup @ z + b2) -> flat[464]: ONE thread per row n computes all
    // 4 outputs (sup row read once, z read as broadcast float4 -> ~4x fewer
    // LDS wavefronts than the (n,o)-per-thread version).
    if (tid < NN) {
        int n = tid;
        float a0 = 0.f, a1 = 0.f, a2 = 0.f, a3 = 0.f;
        #pragma unroll
        for (int u = 0; u < 16; u++) {
            uint4 uw = *(const uint4*)(smc + OFF_T2 + SWZ((uint32_t)(n * RB + u * 16)));
            uint32_t wv[4] = {uw.x, uw.y, uw.z, uw.w};
            #pragma unroll
            for (int p = 0; p < 4; p++) {
                int m0 = u * 8 + p * 2;
                float s0 = bf_lo(wv[p]);
                float s1 = bf_hi(wv[p]);
                float4 z0 = *(const float4*)&s_z[m0 * 4];
                float4 z1 = *(const float4*)&s_z[(m0 + 1) * 4];
                a0 += s0 * z0.x + s1 * z1.x;
                a1 += s0 * z0.y + s1 * z1.y;
                a2 += s0 * z0.z + s1 * z1.z;
                a3 += s0 * z0.w + s1 * z1.w;
            }
        }
        float4 r4;
        r4.x = fmaxf(a0 + b2[0], 0.f);
        r4.y = fmaxf(a1 + b2[1], 0.f);
        r4.z = fmaxf(a2 + b2[2], 0.f);
        r4.w = fmaxf(a3 + b2[3], 0.f);
        *(float4*)&s_flat[n * 4] = r4;
    } else if (tid < 128) {
        *(float4*)&s_flat[tid * 4] = make_float4(0.f, 0.f, 0.f, 0.f);
    }
    __syncthreads();

    // r = relu(flat @ Wr1 + br1): warp w handles j = w*4..w*4+3; 32 lanes read
    // one 2KB row of Wr1^T coalesced (float4) and shfl-reduce.
    {
        const float4* fl4 = (const float4*)s_flat;   // 128 float4
        #pragma unroll
        for (int jj = 0; jj < 4; ++jj) {
            int j = warp * 4 + jj;
            const float4* wrow = (const float4*)(g_wr1t + (size_t)j * 512);
            float a = 0.f;
            #pragma unroll
            for (int u = 0; u < 4; ++u) {
                float4 w4 = wrow[lane + u * 32];
                float4 f4 = fl4[lane + u * 32];
                a += w4.x * f4.x + w4.y * f4.y + w4.z * f4.z + w4.w * f4.w;
            }
            a += __shfl_xor_sync(0xffffffffu, a, 16);
            a += __shfl_xor_sync(0xffffffffu, a, 8);
            a += __shfl_xor_sync(0xffffffffu, a, 4);
            a += __shfl_xor_sync(0xffffffffu, a, 2);
            a += __shfl_xor_sync(0xffffffffu, a, 1);
            if (lane == 0) s_r[j] = fmaxf(a + br1[j], 0.f);
        }
    }
    __syncthreads();

    // logits = r @ Wr2 + br2 ; log_softmax (2 classes)
    if (tid < 64) {
        float rv = s_r[tid];
        float p0 = rv * Wr2[tid * 2 + 0];
        float p1 = rv * Wr2[tid * 2 + 1];
        #pragma unroll
        for (int m = 16; m >= 1; m >>= 1) {
            p0 += __shfl_xor_sync(0xffffffffu, p0, m);
            p1 += __shfl_xor_sync(0xffffffffu, p1, m);
        }
        if ((tid & 31) == 0) {
            s_red[(tid >> 5) * 2 + 0] = p0;
            s_red[(tid >> 5) * 2 + 1] = p1;
        }
    }
    __syncthreads();
    if (tid == 0) {
        float l0 = s_red[0] + s_red[2] + br2[0];
        float l1 = s_red[1] + s_red[3] + br2[1];
        float mx = fmaxf(l0, l1);
        float lse = mx + logf(expf(l0 - mx) + expf(l1 - mx));
        out[(size_t)b * 2 + 0] = l0 - lse;
        out[(size_t)b * 2 + 1] = l1 - lse;
    }
}

extern "C" void kernel_launch(void* const* d_in, const int* in_sizes, int n_in,
                              void* d_out, int out_size) {
    const float* x   = (const float*)d_in[0];
    const float* sup = (const float*)d_in[1];
    const float* W1  = (const float*)d_in[2];
    const float* b1  = (const float*)d_in[3];
    const float* W2  = (const float*)d_in[4];
    const float* b2  = (const float*)d_in[5];
    const float* Wr1 = (const float*)d_in[6];
    const float* br1 = (const float*)d_in[7];
    const float* Wr2 = (const float*)d_in[8];
    const float* br2 = (const float*)d_in[9];
    float* out = (float*)d_out;

    int B = in_sizes[0] / (NN * FIN);

    prep_weights<<<(16384 + 64 * 512 + 255) / 256, 256>>>(W1, Wr1);

    cudaFuncSetAttribute(gcn_mma, cudaFuncAttributeMaxDynamicSharedMemorySize, SMEM_BYTES);
    gcn_mma<<<B, NTHR, SMEM_BYTES>>>(x, sup, W1, b1, W2, b2, Wr1, br1, Wr2, br2, out);
}

// round 16
// speedup vs baseline: 2.3965x; 1.0003x over previous
#include <cuda_runtime.h>
#include <cuda_bf16.h>
#include <cuda_fp16.h>
#include <cstdint>

#define NN   116
#define FIN  116
#define HIDD 256
#define RB   256                        // tile row bytes (128 bf16)
#define TILEB (128 * RB)                // 32768
#define NTHR 512

// swizzle for 256B-pitch tiles: spreads row%8 across banks, keeps 16B units
#define SWZ(o) ((uint32_t)(o) ^ (((uint32_t)(o) >> 4) & 0x70u))

// ---- SMEM byte offsets (per CTA total 82944 -> 2 CTAs/SM) ----
#define OFF_T1    0                        // x tile -> sx tile (tail scratch later)
#define OFF_T2    TILEB                    // sup tile
#define OFF_W2    (2 * TILEB)              // 256*4 f32 = 4096
#define OFF_B1V   (OFF_W2 + 4096)          // 256 f32
#define OFF_Z     (OFF_B1V + 1024)         // 128*4 f32 = 2048
#define OFF_ZP    (OFF_Z + 2048)           // 4*128*4 f32 = 8192
#define SMEM_BYTES (OFF_ZP + 8192)         // 82944

// tail scratch overlaid in T1 (sx dead after GEMM_B)
#define OFF_FLAT  OFF_T1                   // 512 f32 (464 + zero pad)
#define OFF_R     (OFF_FLAT + 2048)        // 64 f32
#define OFF_RED   (OFF_R + 256)            // 16 f32

// W1 fragment image: uint32 regs, index = ((((half*4+wc)*8+ks)*2+grp)*32+lane)*4+u
__device__ uint32_t g_w1frag[16384];       // 64KB
// pre-transposed Wr1^T in fp16: [64 rows j][512 cols i] (i >= 464 zero) = 64KB
__device__ __half g_wr1t[64 * 512];

__device__ __forceinline__ uint32_t smem_u32(const void* p) {
    uint32_t a;
    asm("{ .reg .u64 t; cvta.to.shared.u64 t, %1; cvt.u32.u64 %0, t; }" : "=r"(a) : "l"(p));
    return a;
}
__device__ __forceinline__ uint32_t pack_bf16(float a, float b) {
    __nv_bfloat162 v = __float22bfloat162_rn(make_float2(a, b));
    return *(uint32_t*)&v;
}
__device__ __forceinline__ float bf_lo(uint32_t w) {
    return __bfloat162float(__ushort_as_bfloat16((unsigned short)(w & 0xffff)));
}
__device__ __forceinline__ float bf_hi(uint32_t w) {
    return __bfloat162float(__ushort_as_bfloat16((unsigned short)(w >> 16)));
}

#define LDSM_X4(r0, r1, r2, r3, addr) \
    asm volatile("ldmatrix.sync.aligned.m8n8.x4.shared.b16 {%0,%1,%2,%3}, [%4];" \
        : "=r"(r0), "=r"(r1), "=r"(r2), "=r"(r3) : "r"(addr))
#define LDSM_X4T(r0, r1, r2, r3, addr) \
    asm volatile("ldmatrix.sync.aligned.m8n8.x4.trans.shared.b16 {%0,%1,%2,%3}, [%4];" \
        : "=r"(r0), "=r"(r1), "=r"(r2), "=r"(r3) : "r"(addr))

__device__ __forceinline__ void mma16816(float* d, uint32_t a0, uint32_t a1,
                                         uint32_t a2, uint32_t a3,
                                         uint32_t b0, uint32_t b1) {
    asm volatile(
        "mma.sync.aligned.m16n8k16.row.col.f32.bf16.bf16.f32 "
        "{%0,%1,%2,%3}, {%4,%5,%6,%7}, {%8,%9}, {%0,%1,%2,%3};"
        : "+f"(d[0]), "+f"(d[1]), "+f"(d[2]), "+f"(d[3])
        : "r"(a0), "r"(a1), "r"(a2), "r"(a3), "r"(b0), "r"(b1));
}

// GEMM, warp tile 32x32, B from SMEM K-major [k][n] via trans LDSM (GEMM_A)
__device__ __forceinline__ void mma32(float acc[2][4][4],
                                      uint32_t aTile, uint32_t bTile,
                                      int r0, int c0, int lane) {
    const int row_in = (lane & 7) | (((lane >> 3) & 1) << 3);
    const int col_in = (lane >> 4) << 3;
    const uint32_t aRel0 = (uint32_t)((r0 + row_in) * RB + col_in * 2);
    const uint32_t aRel1 = aRel0 + 16 * RB;
    const uint32_t mA0 = (aRel0 >> 4) & 0x70u;
    const uint32_t mA1 = (aRel1 >> 4) & 0x70u;
    const uint32_t bRel0 = (uint32_t)(row_in * RB + (c0 + col_in) * 2);
    const uint32_t bRel1 = bRel0 + 32;
    uint32_t b0 = bTile + SWZ(bRel0);
    uint32_t b1 = bTile + SWZ(bRel1);
    #pragma unroll
    for (int k = 0; k < 8; ++k) {
        const uint32_t ca = (uint32_t)(k * 32);
        uint32_t a0, a1, a2, a3, a4, a5, a6, a7;
        LDSM_X4(a0, a1, a2, a3, aTile + ((aRel0 + ca) ^ mA0));
        LDSM_X4(a4, a5, a6, a7, aTile + ((aRel1 + ca) ^ mA1));
        uint32_t p0, p1, p2, p3, q0, q1, q2, q3;
        LDSM_X4T(p0, p1, p2, p3, b0);
        LDSM_X4T(q0, q1, q2, q3, b1);
        mma16816(acc[0][0], a0, a1, a2, a3, p0, p1);
        mma16816(acc[0][1], a0, a1, a2, a3, p2, p3);
        mma16816(acc[0][2], a0, a1, a2, a3, q0, q1);
        mma16816(acc[0][3], a0, a1, a2, a3, q2, q3);
        mma16816(acc[1][0], a4, a5, a6, a7, p0, p1);
        mma16816(acc[1][1], a4, a5, a6, a7, p2, p3);
        mma16816(acc[1][2], a4, a5, a6, a7, q0, q1);
        mma16816(acc[1][3], a4, a5, a6, a7, q2, q3);
        b0 += 16 * RB;      // +16 k-rows (mask bits invariant)
        b1 += 16 * RB;
    }
}

// GEMM, warp tile 32x32, B fragments streamed from global image via LDG.128
__device__ __forceinline__ void mma32_gB(float acc[2][4][4],
                                         uint32_t aTile, const uint4* wfrag,
                                         int r0, int lane) {
    const int row_in = (lane & 7) | (((lane >> 3) & 1) << 3);
    const int col_in = (lane >> 4) << 3;
    const uint32_t aRel0 = (uint32_t)((r0 + row_in) * RB + col_in * 2);
    const uint32_t aRel1 = aRel0 + 16 * RB;
    const uint32_t mA0 = (aRel0 >> 4) & 0x70u;
    const uint32_t mA1 = (aRel1 >> 4) & 0x70u;
    #pragma unroll
    for (int k = 0; k < 8; ++k) {
        const uint32_t ca = (uint32_t)(k * 32);
        uint32_t a0, a1, a2, a3, a4, a5, a6, a7;
        LDSM_X4(a0, a1, a2, a3, aTile + ((aRel0 + ca) ^ mA0));
        LDSM_X4(a4, a5, a6, a7, aTile + ((aRel1 + ca) ^ mA1));
        uint4 g0 = wfrag[k * 64 + lane];        // regs p0..p3 (coalesced 512B)
        uint4 g1 = wfrag[k * 64 + 32 + lane];   // regs q0..q3
        mma16816(acc[0][0], a0, a1, a2, a3, g0.x, g0.y);
        mma16816(acc[0][1], a0, a1, a2, a3, g0.z, g0.w);
        mma16816(acc[0][2], a0, a1, a2, a3, g1.x, g1.y);
        mma16816(acc[0][3], a0, a1, a2, a3, g1.z, g1.w);
        mma16816(acc[1][0], a4, a5, a6, a7, g0.x, g0.y);
        mma16816(acc[1][1], a4, a5, a6, a7, g0.z, g0.w);
        mma16816(acc[1][2], a4, a5, a6, a7, g1.x, g1.y);
        mma16816(acc[1][3], a4, a5, a6, a7, g1.z, g1.w);
    }
}

// ---- fused prep: W1 fragment image + Wr1^T fp16 (idempotent) ----
__global__ void prep_weights(const float* __restrict__ W1,
                             const float* __restrict__ Wr1) {
    int idx = blockIdx.x * blockDim.x + threadIdx.x;
    if (idx < 16384) {
        int u    = idx & 3;
        int lane = (idx >> 2) & 31;
        int grp  = (idx >> 7) & 1;
        int ks   = (idx >> 8) & 7;
        int wc   = (idx >> 11) & 3;
        int half = idx >> 13;
        int r = grp * 4 + u;
        int k = ks * 16 + (r & 1) * 8 + (lane & 3) * 2;
        int h = half * 128 + wc * 32 + (r >> 1) * 8 + (lane >> 2);
        float v0 = (k     < FIN) ? W1[(size_t)k * HIDD + h]       : 0.f;
        float v1 = (k + 1 < FIN) ? W1[(size_t)(k + 1) * HIDD + h] : 0.f;
        g_w1frag[idx] = pack_bf16(v0, v1);
    } else if (idx < 16384 + 64 * 512) {
        int q = idx - 16384;
        int j = q >> 9, i = q & 511;
        g_wr1t[q] = __float2half_rn((i < 464) ? Wr1[(size_t)i * 64 + j] : 0.f);
    }
}

extern __shared__ char smc[];

__global__ void __launch_bounds__(NTHR, 2) gcn_mma(
    const float* __restrict__ x,   const float* __restrict__ sup,
    const float* __restrict__ W1,  const float* __restrict__ b1,
    const float* __restrict__ W2,  const float* __restrict__ b2,
    const float* __restrict__ Wr1, const float* __restrict__ br1,
    const float* __restrict__ Wr2, const float* __restrict__ br2,
    float* __restrict__ out)
{
    const int tid  = threadIdx.x;
    const int b    = blockIdx.x;
    const int lane = tid & 31;
    const int warp = tid >> 5;            // 0..15
    const int r0   = (warp >> 2) * 32;    // 4 row blocks
    const int c0   = (warp & 3) * 32;     // 4 col blocks
    const int wc   = warp & 3;

    float* s_w2   = (float*)(smc + OFF_W2);
    float* s_b1   = (float*)(smc + OFF_B1V);
    float* s_z    = (float*)(smc + OFF_Z);
    float* s_zp   = (float*)(smc + OFF_ZP);
    float* s_flat = (float*)(smc + OFF_FLAT);
    float* s_r    = (float*)(smc + OFF_R);
    float* s_red  = (float*)(smc + OFF_RED);

    const uint32_t su = smem_u32(smc);

    // zero ONLY the pad regions of x/sup tiles:
    //  (a) full rows 116..127
    const uint4 z4 = make_uint4(0, 0, 0, 0);
    for (int i = tid; i < 12 * 16 * 2; i += NTHR) {
        int t   = i / (12 * 16);
        int rem = i % (12 * 16);
        int m = 116 + (rem >> 4), u = rem & 15;
        *(uint4*)(smc + (t ? OFF_T2 : OFF_T1) + (uint32_t)(m * RB + u * 16)) = z4;
    }
    //  (b) cols 112..127 of rows 0..115 (2 swizzled 16B units; converter
    //      overwrites bytes 224..231 after the barrier)
    for (int i = tid; i < 116 * 2 * 2; i += NTHR) {
        int t   = i & 1;
        int rem = i >> 1;
        int m = rem >> 1, u = rem & 1;
        uint32_t off = SWZ((uint32_t)(m * RB + 224 + u * 16));
        *(uint4*)(smc + (t ? OFF_T2 : OFF_T1) + off) = z4;
    }
    for (int i = tid; i < HIDD * 4; i += NTHR) s_w2[i] = W2[i];
    for (int i = tid; i < HIDD; i += NTHR)     s_b1[i] = b1[i];
    __syncthreads();

    // load + convert x[b], sup[b] -> bf16 swizzled tiles [m][k]
    const float* xb = x   + (size_t)b * NN * FIN;
    const float* sb = sup + (size_t)b * NN * NN;
    for (int q = tid; q < NN * 29; q += NTHR) {
        int m = q / 29, c4 = (q % 29) * 4;
        uint32_t off = SWZ((uint32_t)(m * RB + c4 * 2));
        float4 vx = *(const float4*)(xb + m * FIN + c4);
        uint2 w;
        w.x = pack_bf16(vx.x, vx.y);
        w.y = pack_bf16(vx.z, vx.w);
        *(uint2*)(smc + OFF_T1 + off) = w;
        float4 vs = *(const float4*)(sb + m * NN + c4);
        w.x = pack_bf16(vs.x, vs.y);
        w.y = pack_bf16(vs.z, vs.w);
        *(uint2*)(smc + OFF_T2 + off) = w;
    }
    __syncthreads();

    // ---- GEMM_A: sx = sup @ x  (A = T2, B = T1 K-major, trans LDSM) ----
    {
        float acc[2][4][4];
        #pragma unroll
        for (int i = 0; i < 2; i++)
            #pragma unroll
            for (int j = 0; j < 4; j++)
                #pragma unroll
                for (int d = 0; d < 4; d++) acc[i][j][d] = 0.f;

        mma32(acc, su + OFF_T2, su + OFF_T1, r0, c0, lane);
        __syncthreads();   // all x reads done before overwrite

        // store sx as bf16 into T1 ([n][f] layout = A of GEMM_B)
        int grow = lane >> 2, gcol = (lane & 3) * 2;
        #pragma unroll
        for (int i = 0; i < 2; i++) {
            #pragma unroll
            for (int j = 0; j < 4; j++) {
                int rr = r0 + i * 16 + grow;
                int cc = c0 + j * 8 + gcol;
                *(uint32_t*)(smc + OFF_T1 + SWZ((uint32_t)(rr * RB + cc * 2))) =
                    pack_bf16(acc[i][j][0], acc[i][j][1]);
                *(uint32_t*)(smc + OFF_T1 + SWZ((uint32_t)((rr + 8) * RB + cc * 2))) =
                    pack_bf16(acc[i][j][2], acc[i][j][3]);
            }
        }
    }
    __syncthreads();

    // ---- GEMM_B both halves, no internal syncs (B frags from global) ----
    #pragma unroll
    for (int half = 0; half < 2; ++half) {
        float acc[2][4][4];
        #pragma unroll
        for (int i = 0; i < 2; i++)
            #pragma unroll
            for (int j = 0; j < 4; j++)
                #pragma unroll
                for (int d = 0; d < 4; d++) acc[i][j][d] = 0.f;

        const uint4* wfrag = (const uint4*)g_w1frag + (size_t)(half * 4 + wc) * 512;
        mma32_gB(acc, su + OFF_T1, wfrag, r0, lane);

        // epilogue: relu(h1 + b1) contracted with W2 -> zacc -> s_zp
        // (zacc lives ONLY inside this half: keeps regs at 64, no spills)
        float zacc[4][4];
        #pragma unroll
        for (int s = 0; s < 4; s++)
            #pragma unroll
            for (int o = 0; o < 4; o++) zacc[s][o] = 0.f;
        {
            int gcol = (lane & 3) * 2;
            #pragma unroll
            for (int i = 0; i < 2; i++) {
                #pragma unroll
                for (int j = 0; j < 4; j++) {
                    int h = half * 128 + c0 + j * 8 + gcol;
                    float b1a = s_b1[h], b1b = s_b1[h + 1];
                    float4 wa = *(const float4*)&s_w2[h * 4];
                    float4 wb = *(const float4*)&s_w2[(h + 1) * 4];
                    float v0 = fmaxf(acc[i][j][0] + b1a, 0.f);
                    float v1 = fmaxf(acc[i][j][1] + b1b, 0.f);
                    float v2 = fmaxf(acc[i][j][2] + b1a, 0.f);
                    float v3 = fmaxf(acc[i][j][3] + b1b, 0.f);
                    zacc[i*2+0][0] += v0 * wa.x + v1 * wb.x;
                    zacc[i*2+0][1] += v0 * wa.y + v1 * wb.y;
                    zacc[i*2+0][2] += v0 * wa.z + v1 * wb.z;
                    zacc[i*2+0][3] += v0 * wa.w + v1 * wb.w;
                    zacc[i*2+1][0] += v2 * wa.x + v3 * wb.x;
                    zacc[i*2+1][1] += v2 * wa.y + v3 * wb.y;
                    zacc[i*2+1][2] += v2 * wa.z + v3 * wb.z;
                    zacc[i*2+1][3] += v2 * wa.w + v3 * wb.w;
                }
            }
        }
        // reduce over the 4 lanes sharing the same rows; half0 assigns, half1 adds
        #pragma unroll
        for (int s = 0; s < 4; s++) {
            #pragma unroll
            for (int o = 0; o < 4; o++) {
                float v = zacc[s][o];
                v += __shfl_xor_sync(0xffffffffu, v, 1);
                v += __shfl_xor_sync(0xffffffffu, v, 2);
                zacc[s][o] = v;
            }
        }
        if ((lane & 3) == 0) {
            #pragma unroll
            for (int s = 0; s < 4; s++) {
                int rr = r0 + (s >> 1) * 16 + (lane >> 2) + (s & 1) * 8;
                #pragma unroll
                for (int o = 0; o < 4; o++) {
                    float* dst = &s_zp[(wc * 128 + rr) * 4 + o];
                    if (half == 0) *dst = zacc[s][o];
                    else           *dst += zacc[s][o];
                }
            }
        }
    }
    __syncthreads();   // GEMMs done; T1 becomes tail scratch

    // z[n][o] = sum over the 4 column-group partials
    {
        int n = tid >> 2, o = tid & 3;   // exactly 512 items
        s_z[n * 4 + o] = s_zp[(0 * 128 + n) * 4 + o] + s_zp[(1 * 128 + n) * 4 + o]
                       + s_zp[(2 * 128 + n) * 4 + o] + s_zp[(3 * 128 + n) * 4 + o];
    }
    __syncthreads();

    // h2 = relu(sup @ z + b2) -> flat[464]: ONE thread per row n computes all
    // 4 outputs (sup row read once, z read as broadcast float4)
    if (tid < NN) {
        int n = tid;
        float a0 = 0.f, a1 = 0.f, a2 = 0.f, a3 = 0.f;
        #pragma unroll
        for (int u = 0; u < 16; u++) {
            uint4 uw = *(const uint4*)(smc + OFF_T2 + SWZ((uint32_t)(n * RB + u * 16)));
            uint32_t wv[4] = {uw.x, uw.y, uw.z, uw.w};
            #pragma unroll
            for (int p = 0; p < 4; p++) {
                int m0 = u * 8 + p * 2;
                float s0 = bf_lo(wv[p]);
                float s1 = bf_hi(wv[p]);
                float4 z0 = *(const float4*)&s_z[m0 * 4];
                float4 z1 = *(const float4*)&s_z[(m0 + 1) * 4];
                a0 += s0 * z0.x + s1 * z1.x;
                a1 += s0 * z0.y + s1 * z1.y;
                a2 += s0 * z0.z + s1 * z1.z;
                a3 += s0 * z0.w + s1 * z1.w;
            }
        }
        float4 r4;
        r4.x = fmaxf(a0 + b2[0], 0.f);
        r4.y = fmaxf(a1 + b2[1], 0.f);
        r4.z = fmaxf(a2 + b2[2], 0.f);
        r4.w = fmaxf(a3 + b2[3], 0.f);
        *(float4*)&s_flat[n * 4] = r4;
    } else if (tid < 128) {
        *(float4*)&s_flat[tid * 4] = make_float4(0.f, 0.f, 0.f, 0.f);
    }
    __syncthreads();

    // r = relu(flat @ Wr1 + br1): warp w handles j = w*4..w*4+3; 32 lanes read
    // one 1KB fp16 row of Wr1^T coalesced (uint4 = 8 halfs) and shfl-reduce.
    {
        const float4* fl4 = (const float4*)s_flat;   // 128 float4
        #pragma unroll
        for (int jj = 0; jj < 4; ++jj) {
            int j = warp * 4 + jj;
            const uint4* wrow = (const uint4*)(g_wr1t + (size_t)j * 512);
            float a = 0.f;
            #pragma unroll
            for (int u = 0; u < 2; ++u) {
                uint4 wp = wrow[lane + u * 32];          // 8 fp16 weights
                float4 f0 = fl4[(lane + u * 32) * 2];     // flat 8 floats
                float4 f1 = fl4[(lane + u * 32) * 2 + 1];
                __half2 h0 = *(__half2*)&wp.x;
                __half2 h1 = *(__half2*)&wp.y;
                __half2 h2 = *(__half2*)&wp.z;
                __half2 h3 = *(__half2*)&wp.w;
                float2 w0 = __half22float2(h0);
                float2 w1 = __half22float2(h1);
                float2 w2 = __half22float2(h2);
                float2 w3 = __half22float2(h3);
                a += w0.x * f0.x + w0.y * f0.y + w1.x * f0.z + w1.y * f0.w;
                a += w2.x * f1.x + w2.y * f1.y + w3.x * f1.z + w3.y * f1.w;
            }
            a += __shfl_xor_sync(0xffffffffu, a, 16);
            a += __shfl_xor_sync(0xffffffffu, a, 8);
            a += __shfl_xor_sync(0xffffffffu, a, 4);
            a += __shfl_xor_sync(0xffffffffu, a, 2);
            a += __shfl_xor_sync(0xffffffffu, a, 1);
            if (lane == 0) s_r[j] = fmaxf(a + br1[j], 0.f);
        }
    }
    __syncthreads();

    // logits = r @ Wr2 + br2 ; log_softmax (2 classes)
    if (tid < 64) {
        float rv = s_r[tid];
        float p0 = rv * Wr2[tid * 2 + 0];
        float p1 = rv * Wr2[tid * 2 + 1];
        #pragma unroll
        for (int m = 16; m >= 1; m >>= 1) {
            p0 += __shfl_xor_sync(0xffffffffu, p0, m);
            p1 += __shfl_xor_sync(0xffffffffu, p1, m);
        }
        if ((tid & 31) == 0) {
            s_red[(tid >> 5) * 2 + 0] = p0;
            s_red[(tid >> 5) * 2 + 1] = p1;
        }
    }
    __syncthreads();
    if (tid == 0) {
        float l0 = s_red[0] + s_red[2] + br2[0];
        float l1 = s_red[1] + s_red[3] + br2[1];
        float mx = fmaxf(l0, l1);
        float lse = mx + logf(expf(l0 - mx) + expf(l1 - mx));
        out[(size_t)b * 2 + 0] = l0 - lse;
        out[(size_t)b * 2 + 1] = l1 - lse;
    }
}

extern "C" void kernel_launch(void* const* d_in, const int* in_sizes, int n_in,
                              void* d_out, int out_size) {
    const float* x   = (const float*)d_in[0];
    const float* sup = (const float*)d_in[1];
    const float* W1  = (const float*)d_in[2];
    const float* b1  = (const float*)d_in[3];
    const float* W2  = (const float*)d_in[4];
    const float* b2  = (const float*)d_in[5];
    const float* Wr1 = (const float*)d_in[6];
    const float* br1 = (const float*)d_in[7];
    const float* Wr2 = (const float*)d_in[8];
    const float* br2 = (const float*)d_in[9];
    float* out = (float*)d_out;

    int B = in_sizes[0] / (NN * FIN);

    prep_weights<<<(16384 + 64 * 512 + 255) / 256, 256>>>(W1, Wr1);

    cudaFuncSetAttribute(gcn_mma, cudaFuncAttributeMaxDynamicSharedMemorySize, SMEM_BYTES);
    gcn_mma<<<B, NTHR, SMEM_BYTES>>>(x, sup, W1, b1, W2, b2, Wr1, br1, Wr2, br2, out);
}

// round 17
// speedup vs baseline: 2.5493x; 1.0638x over previous
#include <cuda_runtime.h>
#include <cuda_bf16.h>
#include <cuda_fp16.h>
#include <cstdint>

#define NN   116
#define FIN  116
#define HIDD 256
#define RB   256                        // tile row bytes (128 bf16)
#define TILEB (128 * RB)                // 32768
#define NTHR 512
#define NSLOT 7                         // ceil(116*29 / 512)

// swizzle for 256B-pitch tiles: spreads row%8 across banks, keeps 16B units
#define SWZ(o) ((uint32_t)(o) ^ (((uint32_t)(o) >> 4) & 0x70u))

// ---- SMEM byte offsets (per CTA total 82944 -> 2 CTAs/SM) ----
#define OFF_T1    0                        // x tile -> sx tile (tail scratch later)
#define OFF_T2    TILEB                    // sup tile
#define OFF_W2    (2 * TILEB)              // 256*4 f32 = 4096
#define OFF_B1V   (OFF_W2 + 4096)          // 256 f32
#define OFF_Z     (OFF_B1V + 1024)         // 128*4 f32 = 2048
#define OFF_ZP    (OFF_Z + 2048)           // 4*128*4 f32 = 8192
#define SMEM_BYTES (OFF_ZP + 8192)         // 82944

// tail scratch overlaid in T1 (sx dead after GEMM_B)
#define OFF_FLAT  OFF_T1                   // 512 f32 (464 + zero pad)
#define OFF_R     (OFF_FLAT + 2048)        // 64 f32
#define OFF_RED   (OFF_R + 256)            // 16 f32

// W1 fragment image: uint32 regs, index = ((((half*4+wc)*8+ks)*2+grp)*32+lane)*4+u
__device__ uint32_t g_w1frag[16384];       // 64KB
// pre-transposed Wr1^T in fp16: [64 rows j][512 cols i] (i >= 464 zero) = 64KB
__device__ __half g_wr1t[64 * 512];

__device__ __forceinline__ uint32_t smem_u32(const void* p) {
    uint32_t a;
    asm("{ .reg .u64 t; cvta.to.shared.u64 t, %1; cvt.u32.u64 %0, t; }" : "=r"(a) : "l"(p));
    return a;
}
__device__ __forceinline__ uint32_t pack_bf16(float a, float b) {
    __nv_bfloat162 v = __float22bfloat162_rn(make_float2(a, b));
    return *(uint32_t*)&v;
}
__device__ __forceinline__ float bf_lo(uint32_t w) {
    return __bfloat162float(__ushort_as_bfloat16((unsigned short)(w & 0xffff)));
}
__device__ __forceinline__ float bf_hi(uint32_t w) {
    return __bfloat162float(__ushort_as_bfloat16((unsigned short)(w >> 16)));
}

#define LDSM_X4(r0, r1, r2, r3, addr) \
    asm volatile("ldmatrix.sync.aligned.m8n8.x4.shared.b16 {%0,%1,%2,%3}, [%4];" \
        : "=r"(r0), "=r"(r1), "=r"(r2), "=r"(r3) : "r"(addr))
#define LDSM_X4T(r0, r1, r2, r3, addr) \
    asm volatile("ldmatrix.sync.aligned.m8n8.x4.trans.shared.b16 {%0,%1,%2,%3}, [%4];" \
        : "=r"(r0), "=r"(r1), "=r"(r2), "=r"(r3) : "r"(addr))

__device__ __forceinline__ void mma16816(float* d, uint32_t a0, uint32_t a1,
                                         uint32_t a2, uint32_t a3,
                                         uint32_t b0, uint32_t b1) {
    asm volatile(
        "mma.sync.aligned.m16n8k16.row.col.f32.bf16.bf16.f32 "
        "{%0,%1,%2,%3}, {%4,%5,%6,%7}, {%8,%9}, {%0,%1,%2,%3};"
        : "+f"(d[0]), "+f"(d[1]), "+f"(d[2]), "+f"(d[3])
        : "r"(a0), "r"(a1), "r"(a2), "r"(a3), "r"(b0), "r"(b1));
}

// GEMM, warp tile 32x32, B from SMEM K-major [k][n] via trans LDSM (GEMM_A)
__device__ __forceinline__ void mma32(float acc[2][4][4],
                                      uint32_t aTile, uint32_t bTile,
                                      int r0, int c0, int lane) {
    const int row_in = (lane & 7) | (((lane >> 3) & 1) << 3);
    const int col_in = (lane >> 4) << 3;
    const uint32_t aRel0 = (uint32_t)((r0 + row_in) * RB + col_in * 2);
    const uint32_t aRel1 = aRel0 + 16 * RB;
    const uint32_t mA0 = (aRel0 >> 4) & 0x70u;
    const uint32_t mA1 = (aRel1 >> 4) & 0x70u;
    const uint32_t bRel0 = (uint32_t)(row_in * RB + (c0 + col_in) * 2);
    const uint32_t bRel1 = bRel0 + 32;
    uint32_t b0 = bTile + SWZ(bRel0);
    uint32_t b1 = bTile + SWZ(bRel1);
    #pragma unroll
    for (int k = 0; k < 8; ++k) {
        const uint32_t ca = (uint32_t)(k * 32);
        uint32_t a0, a1, a2, a3, a4, a5, a6, a7;
        LDSM_X4(a0, a1, a2, a3, aTile + ((aRel0 + ca) ^ mA0));
        LDSM_X4(a4, a5, a6, a7, aTile + ((aRel1 + ca) ^ mA1));
        uint32_t p0, p1, p2, p3, q0, q1, q2, q3;
        LDSM_X4T(p0, p1, p2, p3, b0);
        LDSM_X4T(q0, q1, q2, q3, b1);
        mma16816(acc[0][0], a0, a1, a2, a3, p0, p1);
        mma16816(acc[0][1], a0, a1, a2, a3, p2, p3);
        mma16816(acc[0][2], a0, a1, a2, a3, q0, q1);
        mma16816(acc[0][3], a0, a1, a2, a3, q2, q3);
        mma16816(acc[1][0], a4, a5, a6, a7, p0, p1);
        mma16816(acc[1][1], a4, a5, a6, a7, p2, p3);
        mma16816(acc[1][2], a4, a5, a6, a7, q0, q1);
        mma16816(acc[1][3], a4, a5, a6, a7, q2, q3);
        b0 += 16 * RB;      // +16 k-rows (mask bits invariant)
        b1 += 16 * RB;
    }
}

// GEMM, warp tile 32x32, B fragments streamed from global image via LDG.128
__device__ __forceinline__ void mma32_gB(float acc[2][4][4],
                                         uint32_t aTile, const uint4* wfrag,
                                         int r0, int lane) {
    const int row_in = (lane & 7) | (((lane >> 3) & 1) << 3);
    const int col_in = (lane >> 4) << 3;
    const uint32_t aRel0 = (uint32_t)((r0 + row_in) * RB + col_in * 2);
    const uint32_t aRel1 = aRel0 + 16 * RB;
    const uint32_t mA0 = (aRel0 >> 4) & 0x70u;
    const uint32_t mA1 = (aRel1 >> 4) & 0x70u;
    #pragma unroll
    for (int k = 0; k < 8; ++k) {
        const uint32_t ca = (uint32_t)(k * 32);
        uint32_t a0, a1, a2, a3, a4, a5, a6, a7;
        LDSM_X4(a0, a1, a2, a3, aTile + ((aRel0 + ca) ^ mA0));
        LDSM_X4(a4, a5, a6, a7, aTile + ((aRel1 + ca) ^ mA1));
        uint4 g0 = wfrag[k * 64 + lane];        // regs p0..p3 (coalesced 512B)
        uint4 g1 = wfrag[k * 64 + 32 + lane];   // regs q0..q3
        mma16816(acc[0][0], a0, a1, a2, a3, g0.x, g0.y);
        mma16816(acc[0][1], a0, a1, a2, a3, g0.z, g0.w);
        mma16816(acc[0][2], a0, a1, a2, a3, g1.x, g1.y);
        mma16816(acc[0][3], a0, a1, a2, a3, g1.z, g1.w);
        mma16816(acc[1][0], a4, a5, a6, a7, g0.x, g0.y);
        mma16816(acc[1][1], a4, a5, a6, a7, g0.z, g0.w);
        mma16816(acc[1][2], a4, a5, a6, a7, g1.x, g1.y);
        mma16816(acc[1][3], a4, a5, a6, a7, g1.z, g1.w);
    }
}

// ---- fused prep: W1 fragment image + Wr1^T fp16 (idempotent) ----
__global__ void prep_weights(const float* __restrict__ W1,
                             const float* __restrict__ Wr1) {
    int idx = blockIdx.x * blockDim.x + threadIdx.x;
    if (idx < 16384) {
        int u    = idx & 3;
        int lane = (idx >> 2) & 31;
        int grp  = (idx >> 7) & 1;
        int ks   = (idx >> 8) & 7;
        int wc   = (idx >> 11) & 3;
        int half = idx >> 13;
        int r = grp * 4 + u;
        int k = ks * 16 + (r & 1) * 8 + (lane & 3) * 2;
        int h = half * 128 + wc * 32 + (r >> 1) * 8 + (lane >> 2);
        float v0 = (k     < FIN) ? W1[(size_t)k * HIDD + h]       : 0.f;
        float v1 = (k + 1 < FIN) ? W1[(size_t)(k + 1) * HIDD + h] : 0.f;
        g_w1frag[idx] = pack_bf16(v0, v1);
    } else if (idx < 16384 + 64 * 512) {
        int q = idx - 16384;
        int j = q >> 9, i = q & 511;
        g_wr1t[q] = __float2half_rn((i < 464) ? Wr1[(size_t)i * 64 + j] : 0.f);
    }
}

extern __shared__ char smc[];

__global__ void __launch_bounds__(NTHR, 2) gcn_mma(
    const float* __restrict__ x,   const float* __restrict__ sup,
    const float* __restrict__ W1,  const float* __restrict__ b1,
    const float* __restrict__ W2,  const float* __restrict__ b2,
    const float* __restrict__ Wr1, const float* __restrict__ br1,
    const float* __restrict__ Wr2, const float* __restrict__ br2,
    float* __restrict__ out)
{
    const int tid  = threadIdx.x;
    const int b    = blockIdx.x;
    const int lane = tid & 31;
    const int warp = tid >> 5;            // 0..15
    const int r0   = (warp >> 2) * 32;    // 4 row blocks
    const int c0   = (warp & 3) * 32;     // 4 col blocks
    const int wc   = warp & 3;

    float* s_w2   = (float*)(smc + OFF_W2);
    float* s_b1   = (float*)(smc + OFF_B1V);
    float* s_z    = (float*)(smc + OFF_Z);
    float* s_zp   = (float*)(smc + OFF_ZP);
    float* s_flat = (float*)(smc + OFF_FLAT);
    float* s_r    = (float*)(smc + OFF_R);
    float* s_red  = (float*)(smc + OFF_RED);

    const uint32_t su = smem_u32(smc);
    const float* xb = x   + (size_t)b * NN * FIN;
    const float* sb = sup + (size_t)b * NN * NN;

    // precompute this thread's convert slots (shared by x and sup passes)
    int mArr[NSLOT], cArr[NSLOT];
    #pragma unroll
    for (int i = 0; i < NSLOT; i++) {
        int s = tid + i * NTHR;
        int m = s / 29, c4 = (s % 29) * 4;
        mArr[i] = m; cArr[i] = c4;
    }

    // ---- x pass: front-batch ALL LDGs (MLP=7), then convert+store ----
    {
        float4 vx[NSLOT];
        #pragma unroll
        for (int i = 0; i < NSLOT; i++) {
            int s = tid + i * NTHR;
            if (s < NN * 29) vx[i] = *(const float4*)(xb + mArr[i] * FIN + cArr[i]);
        }
        // zero pad regions + small-weight preload while x LDGs are in flight
        const uint4 z4 = make_uint4(0, 0, 0, 0);
        for (int i = tid; i < 12 * 16 * 2; i += NTHR) {
            int t   = i / (12 * 16);
            int rem = i % (12 * 16);
            int m = 116 + (rem >> 4), u = rem & 15;
            *(uint4*)(smc + (t ? OFF_T2 : OFF_T1) + (uint32_t)(m * RB + u * 16)) = z4;
        }
        for (int i = tid; i < 116 * 2 * 2; i += NTHR) {
            int t   = i & 1;
            int rem = i >> 1;
            int m = rem >> 1, u = rem & 1;
            uint32_t off = SWZ((uint32_t)(m * RB + 224 + u * 16));
            *(uint4*)(smc + (t ? OFF_T2 : OFF_T1) + off) = z4;
        }
        for (int i = tid; i < HIDD * 4; i += NTHR) s_w2[i] = W2[i];
        for (int i = tid; i < HIDD; i += NTHR)     s_b1[i] = b1[i];

        #pragma unroll
        for (int i = 0; i < NSLOT; i++) {
            int s = tid + i * NTHR;
            if (s < NN * 29) {
                uint32_t off = SWZ((uint32_t)(mArr[i] * RB + cArr[i] * 2));
                uint2 w;
                w.x = pack_bf16(vx[i].x, vx[i].y);
                w.y = pack_bf16(vx[i].z, vx[i].w);
                *(uint2*)(smc + OFF_T1 + off) = w;
            }
        }
    }
    // ---- sup pass: same deep-MLP structure ----
    {
        float4 vs[NSLOT];
        #pragma unroll
        for (int i = 0; i < NSLOT; i++) {
            int s = tid + i * NTHR;
            if (s < NN * 29) vs[i] = *(const float4*)(sb + mArr[i] * NN + cArr[i]);
        }
        #pragma unroll
        for (int i = 0; i < NSLOT; i++) {
            int s = tid + i * NTHR;
            if (s < NN * 29) {
                uint32_t off = SWZ((uint32_t)(mArr[i] * RB + cArr[i] * 2));
                uint2 w;
                w.x = pack_bf16(vs[i].x, vs[i].y);
                w.y = pack_bf16(vs[i].z, vs[i].w);
                *(uint2*)(smc + OFF_T2 + off) = w;
            }
        }
    }
    __syncthreads();

    // ---- GEMM_A: sx = sup @ x  (A = T2, B = T1 K-major, trans LDSM) ----
    {
        float acc[2][4][4];
        #pragma unroll
        for (int i = 0; i < 2; i++)
            #pragma unroll
            for (int j = 0; j < 4; j++)
                #pragma unroll
                for (int d = 0; d < 4; d++) acc[i][j][d] = 0.f;

        mma32(acc, su + OFF_T2, su + OFF_T1, r0, c0, lane);
        __syncthreads();   // all x reads done before overwrite

        // store sx as bf16 into T1 ([n][f] layout = A of GEMM_B)
        int grow = lane >> 2, gcol = (lane & 3) * 2;
        #pragma unroll
        for (int i = 0; i < 2; i++) {
            #pragma unroll
            for (int j = 0; j < 4; j++) {
                int rr = r0 + i * 16 + grow;
                int cc = c0 + j * 8 + gcol;
                *(uint32_t*)(smc + OFF_T1 + SWZ((uint32_t)(rr * RB + cc * 2))) =
                    pack_bf16(acc[i][j][0], acc[i][j][1]);
                *(uint32_t*)(smc + OFF_T1 + SWZ((uint32_t)((rr + 8) * RB + cc * 2))) =
                    pack_bf16(acc[i][j][2], acc[i][j][3]);
            }
        }
    }
    __syncthreads();

    // ---- GEMM_B both halves, no internal syncs (B frags from global) ----
    #pragma unroll
    for (int half = 0; half < 2; ++half) {
        float acc[2][4][4];
        #pragma unroll
        for (int i = 0; i < 2; i++)
            #pragma unroll
            for (int j = 0; j < 4; j++)
                #pragma unroll
                for (int d = 0; d < 4; d++) acc[i][j][d] = 0.f;

        const uint4* wfrag = (const uint4*)g_w1frag + (size_t)(half * 4 + wc) * 512;
        mma32_gB(acc, su + OFF_T1, wfrag, r0, lane);

        // epilogue: relu(h1 + b1) contracted with W2 -> zacc -> s_zp
        // (zacc lives ONLY inside this half: keeps regs at 64, no spills)
        float zacc[4][4];
        #pragma unroll
        for (int s = 0; s < 4; s++)
            #pragma unroll
            for (int o = 0; o < 4; o++) zacc[s][o] = 0.f;
        {
            int gcol = (lane & 3) * 2;
            #pragma unroll
            for (int i = 0; i < 2; i++) {
                #pragma unroll
                for (int j = 0; j < 4; j++) {
                    int h = half * 128 + c0 + j * 8 + gcol;
                    float b1a = s_b1[h], b1b = s_b1[h + 1];
                    float4 wa = *(const float4*)&s_w2[h * 4];
                    float4 wb = *(const float4*)&s_w2[(h + 1) * 4];
                    float v0 = fmaxf(acc[i][j][0] + b1a, 0.f);
                    float v1 = fmaxf(acc[i][j][1] + b1b, 0.f);
                    float v2 = fmaxf(acc[i][j][2] + b1a, 0.f);
                    float v3 = fmaxf(acc[i][j][3] + b1b, 0.f);
                    zacc[i*2+0][0] += v0 * wa.x + v1 * wb.x;
                    zacc[i*2+0][1] += v0 * wa.y + v1 * wb.y;
                    zacc[i*2+0][2] += v0 * wa.z + v1 * wb.z;
                    zacc[i*2+0][3] += v0 * wa.w + v1 * wb.w;
                    zacc[i*2+1][0] += v2 * wa.x + v3 * wb.x;
                    zacc[i*2+1][1] += v2 * wa.y + v3 * wb.y;
                    zacc[i*2+1][2] += v2 * wa.z + v3 * wb.z;
                    zacc[i*2+1][3] += v2 * wa.w + v3 * wb.w;
                }
            }
        }
        // reduce over the 4 lanes sharing the same rows; half0 assigns, half1 adds
        #pragma unroll
        for (int s = 0; s < 4; s++) {
            #pragma unroll
            for (int o = 0; o < 4; o++) {
                float v = zacc[s][o];
                v += __shfl_xor_sync(0xffffffffu, v, 1);
                v += __shfl_xor_sync(0xffffffffu, v, 2);
                zacc[s][o] = v;
            }
        }
        if ((lane & 3) == 0) {
            #pragma unroll
            for (int s = 0; s < 4; s++) {
                int rr = r0 + (s >> 1) * 16 + (lane >> 2) + (s & 1) * 8;
                #pragma unroll
                for (int o = 0; o < 4; o++) {
                    float* dst = &s_zp[(wc * 128 + rr) * 4 + o];
                    if (half == 0) *dst = zacc[s][o];
                    else           *dst += zacc[s][o];
                }
            }
        }
    }
    __syncthreads();   // GEMMs done; T1 becomes tail scratch

    // z[n][o] = sum over the 4 column-group partials
    {
        int n = tid >> 2, o = tid & 3;   // exactly 512 items
        s_z[n * 4 + o] = s_zp[(0 * 128 + n) * 4 + o] + s_zp[(1 * 128 + n) * 4 + o]
                       + s_zp[(2 * 128 + n) * 4 + o] + s_zp[(3 * 128 + n) * 4 + o];
    }
    __syncthreads();

    // h2 = relu(sup @ z + b2) -> flat[464]: ONE thread per row n computes all
    // 4 outputs (sup row read once, z read as broadcast float4)
    if (tid < NN) {
        int n = tid;
        float a0 = 0.f, a1 = 0.f, a2 = 0.f, a3 = 0.f;
        #pragma unroll
        for (int u = 0; u < 16; u++) {
            uint4 uw = *(const uint4*)(smc + OFF_T2 + SWZ((uint32_t)(n * RB + u * 16)));
            uint32_t wv[4] = {uw.x, uw.y, uw.z, uw.w};
            #pragma unroll
            for (int p = 0; p < 4; p++) {
                int m0 = u * 8 + p * 2;
                float s0 = bf_lo(wv[p]);
                float s1 = bf_hi(wv[p]);
                float4 z0 = *(const float4*)&s_z[m0 * 4];
                float4 z1 = *(const float4*)&s_z[(m0 + 1) * 4];
                a0 += s0 * z0.x + s1 * z1.x;
                a1 += s0 * z0.y + s1 * z1.y;
                a2 += s0 * z0.z + s1 * z1.z;
                a3 += s0 * z0.w + s1 * z1.w;
            }
        }
        float4 r4;
        r4.x = fmaxf(a0 + b2[0], 0.f);
        r4.y = fmaxf(a1 + b2[1], 0.f);
        r4.z = fmaxf(a2 + b2[2], 0.f);
        r4.w = fmaxf(a3 + b2[3], 0.f);
        *(float4*)&s_flat[n * 4] = r4;
    } else if (tid < 128) {
        *(float4*)&s_flat[tid * 4] = make_float4(0.f, 0.f, 0.f, 0.f);
    }
    __syncthreads();

    // r = relu(flat @ Wr1 + br1): warp w handles j = w*4..w*4+3; 32 lanes read
    // one 1KB fp16 row of Wr1^T coalesced (uint4 = 8 halfs) and shfl-reduce.
    {
        const float4* fl4 = (const float4*)s_flat;   // 128 float4
        #pragma unroll
        for (int jj = 0; jj < 4; ++jj) {
            int j = warp * 4 + jj;
            const uint4* wrow = (const uint4*)(g_wr1t + (size_t)j * 512);
            float a = 0.f;
            #pragma unroll
            for (int u = 0; u < 2; ++u) {
                uint4 wp = wrow[lane + u * 32];          // 8 fp16 weights
                float4 f0 = fl4[(lane + u * 32) * 2];     // flat 8 floats
                float4 f1 = fl4[(lane + u * 32) * 2 + 1];
                __half2 h0 = *(__half2*)&wp.x;
                __half2 h1 = *(__half2*)&wp.y;
                __half2 h2 = *(__half2*)&wp.z;
                __half2 h3 = *(__half2*)&wp.w;
                float2 w0 = __half22float2(h0);
                float2 w1 = __half22float2(h1);
                float2 w2 = __half22float2(h2);
                float2 w3 = __half22float2(h3);
                a += w0.x * f0.x + w0.y * f0.y + w1.x * f0.z + w1.y * f0.w;
                a += w2.x * f1.x + w2.y * f1.y + w3.x * f1.z + w3.y * f1.w;
            }
            a += __shfl_xor_sync(0xffffffffu, a, 16);
            a += __shfl_xor_sync(0xffffffffu, a, 8);
            a += __shfl_xor_sync(0xffffffffu, a, 4);
            a += __shfl_xor_sync(0xffffffffu, a, 2);
            a += __shfl_xor_sync(0xffffffffu, a, 1);
            if (lane == 0) s_r[j] = fmaxf(a + br1[j], 0.f);
        }
    }
    __syncthreads();

    // logits = r @ Wr2 + br2 ; log_softmax (2 classes)
    if (tid < 64) {
        float rv = s_r[tid];
        float p0 = rv * Wr2[tid * 2 + 0];
        float p1 = rv * Wr2[tid * 2 + 1];
        #pragma unroll
        for (int m = 16; m >= 1; m >>= 1) {
            p0 += __shfl_xor_sync(0xffffffffu, p0, m);
            p1 += __shfl_xor_sync(0xffffffffu, p1, m);
        }
        if ((tid & 31) == 0) {
            s_red[(tid >> 5) * 2 + 0] = p0;
            s_red[(tid >> 5) * 2 + 1] = p1;
        }
    }
    __syncthreads();
    if (tid == 0) {
        float l0 = s_red[0] + s_red[2] + br2[0];
        float l1 = s_red[1] + s_red[3] + br2[1];
        float mx = fmaxf(l0, l1);
        float lse = mx + logf(expf(l0 - mx) + expf(l1 - mx));
        out[(size_t)b * 2 + 0] = l0 - lse;
        out[(size_t)b * 2 + 1] = l1 - lse;
    }
}

extern "C" void kernel_launch(void* const* d_in, const int* in_sizes, int n_in,
                              void* d_out, int out_size) {
    const float* x   = (const float*)d_in[0];
    const float* sup = (const float*)d_in[1];
    const float* W1  = (const float*)d_in[2];
    const float* b1  = (const float*)d_in[3];
    const float* W2  = (const float*)d_in[4];
    const float* b2  = (const float*)d_in[5];
    const float* Wr1 = (const float*)d_in[6];
    const float* br1 = (const float*)d_in[7];
    const float* Wr2 = (const float*)d_in[8];
    const float* br2 = (const float*)d_in[9];
    float* out = (float*)d_out;

    int B = in_sizes[0] / (NN * FIN);

    prep_weights<<<(16384 + 64 * 512 + 255) / 256, 256>>>(W1, Wr1);

    cudaFuncSetAttribute(gcn_mma, cudaFuncAttributeMaxDynamicSharedMemorySize, SMEM_BYTES);
    gcn_mma<<<B, NTHR, SMEM_BYTES>>>(x, sup, W1, b1, W2, b2, Wr1, br1, Wr2, br2, out);
}